// round 9
// baseline (speedup 1.0000x reference)
#include <cuda_runtime.h>
#include <math.h>
#include <stdint.h>

#define Lq 257
#define Nb 64
#define Dm 768
#define Hh 12
#define HD 64
#define NH (Nb * Hh)               // 768 heads total
#define Mrows (Lq * Nb)            // 16448
#define D3 (3 * Dm)                // 2304
#define LHD (Lq * HD)              // per head per tensor
#define X_ELEMS ((size_t)Mrows * Dm)

// ---------------- scratch (device globals; no allocation allowed) ----------
__device__ float g_h[Mrows * Dm];
__device__ float g_qkv[(size_t)Mrows * D3];   // head-major: [which][nh][l][hd]
__device__ float g_attn[Mrows * Dm];
__device__ float g_x1[Mrows * Dm];
__device__ float g_w_in[(size_t)D3 * Dm];     // tf32-rounded weights
__device__ float g_w_out[(size_t)Dm * Dm];
__device__ float g_w_fc[(size_t)Dm * Dm];

// ---------------- PTX helpers ----------------------------------------------
__device__ __forceinline__ uint32_t f2tf(float f) {
    uint32_t r;
    asm("cvt.rna.tf32.f32 %0, %1;" : "=r"(r) : "f"(f));
    return r;
}
__device__ __forceinline__ float round_tf32(float f) {
    return __uint_as_float(f2tf(f));
}
__device__ __forceinline__ void mma_tf32(float* c, const uint32_t* a, const uint32_t* b) {
    asm volatile(
        "mma.sync.aligned.m16n8k8.row.col.f32.tf32.tf32.f32 "
        "{%0,%1,%2,%3}, {%4,%5,%6,%7}, {%8,%9}, {%0,%1,%2,%3};\n"
        : "+f"(c[0]), "+f"(c[1]), "+f"(c[2]), "+f"(c[3])
        : "r"(a[0]), "r"(a[1]), "r"(a[2]), "r"(a[3]), "r"(b[0]), "r"(b[1]));
}
__device__ __forceinline__ void cp_async16(void* smem, const void* gmem) {
    uint32_t s = (uint32_t)__cvta_generic_to_shared(smem);
    asm volatile("cp.async.ca.shared.global [%0], [%1], 16;\n" :: "r"(s), "l"(gmem));
}
__device__ __forceinline__ void cp_commit() { asm volatile("cp.async.commit_group;\n"); }
__device__ __forceinline__ void cp_wait1()  { asm volatile("cp.async.wait_group 1;\n"); }

// ---------------- weight pre-rounding to tf32 ------------------------------
__global__ void round_w(const float* __restrict__ in, float* __restrict__ out, int n4) {
    int i = blockIdx.x * blockDim.x + threadIdx.x;
    if (i < n4) {
        float4 v = ((const float4*)in)[i];
        v.x = round_tf32(v.x); v.y = round_tf32(v.y);
        v.z = round_tf32(v.z); v.w = round_tf32(v.w);
        ((float4*)out)[i] = v;
    }
}

// ---------------- LayerNorm (output pre-rounded to tf32) -------------------
__global__ void ln_kernel(const float* __restrict__ x,
                          const float* __restrict__ g,
                          const float* __restrict__ b,
                          float* __restrict__ out) {
    int row = blockIdx.x;
    const float* xr = x + (size_t)row * Dm;
    int tid = threadIdx.x;
    float v0 = xr[tid], v1 = xr[tid + 256], v2 = xr[tid + 512];

    __shared__ float red[256];
    red[tid] = v0 + v1 + v2; __syncthreads();
    for (int off = 128; off > 0; off >>= 1) {
        if (tid < off) red[tid] += red[tid + off];
        __syncthreads();
    }
    float mu = red[0] * (1.0f / Dm);
    __syncthreads();

    float d0 = v0 - mu, d1 = v1 - mu, d2 = v2 - mu;
    red[tid] = d0 * d0 + d1 * d1 + d2 * d2; __syncthreads();
    for (int off = 128; off > 0; off >>= 1) {
        if (tid < off) red[tid] += red[tid + off];
        __syncthreads();
    }
    float rstd = rsqrtf(red[0] * (1.0f / Dm) + 1e-5f);

    float* orow = out + (size_t)row * Dm;
    orow[tid]       = round_tf32(d0 * rstd * g[tid]       + b[tid]);
    orow[tid + 256] = round_tf32(d1 * rstd * g[tid + 256] + b[tid + 256]);
    orow[tid + 512] = round_tf32(d2 * rstd * g[tid + 512] + b[tid + 512]);
}

// ---------------- TF32 tensor-core GEMM NT ---------------------------------
// C[M,Nc] = A[M,K] * B[Nc,K]^T (+epilogue). BM=128, BN=128, BK=16.
// A,B are pre-rounded tf32 values (no cvt in mainloop).
// EPI: 2 = +bias +res, 3 = res + quickGELU(C+bias),
//      4 = +bias then scatter into head-major [nh][l][hd]
// Smem-staged epilogue -> fully coalesced stores.
#define SROW 20
#define CPAD 132
#define GEMM_SMEM_FLOATS (128 * CPAD)          // 16896 floats = 67,584 B
#define GEMM_SMEM_BYTES (GEMM_SMEM_FLOATS * 4)

template <int EPI>
__global__ void __launch_bounds__(256) gemm_tc(const float* __restrict__ A,
                                               const float* __restrict__ B,
                                               const float* __restrict__ bias,
                                               const float* __restrict__ res,
                                               float* __restrict__ C,
                                               int K, int Nc, int M) {
    extern __shared__ float smem[];
    // mainloop layout: A stages at [0,5120), B stages at [5120,10240)
    float* Ab[2] = { smem,        smem + 2560 };
    float* Bb[2] = { smem + 5120, smem + 7680 };

    const int t = threadIdx.x;
    const int wid = t >> 5, lane = t & 31;
    const int wm = wid >> 2, wn = wid & 3;
    const int g = lane >> 2, tq = lane & 3;
    const int mBase = blockIdx.y * 128;
    const int nBase = blockIdx.x * 128;

    float acc[4][4][4];
#pragma unroll
    for (int i = 0; i < 4; i++)
#pragma unroll
        for (int j = 0; j < 4; j++)
#pragma unroll
            for (int q = 0; q < 4; q++) acc[i][j][q] = 0.0f;

    const int lr0 = t >> 2, lc0 = (t & 3) * 4;
    const int lr1 = lr0 + 64;

    int arow0 = mBase + lr0; if (arow0 >= M) arow0 = M - 1;
    int arow1 = mBase + lr1; if (arow1 >= M) arow1 = M - 1;
    const float* a0p = A + (size_t)arow0 * K + lc0;
    const float* a1p = A + (size_t)arow1 * K + lc0;
    const float* b0p = B + (size_t)(nBase + lr0) * K + lc0;
    const float* b1p = B + (size_t)(nBase + lr1) * K + lc0;

    const int T = K / 16;

#define LOAD_TILE(stage, k0)                                                  \
    do {                                                                      \
        cp_async16(&Ab[stage][lr0 * SROW + lc0], a0p + (k0));                 \
        cp_async16(&Ab[stage][lr1 * SROW + lc0], a1p + (k0));                 \
        cp_async16(&Bb[stage][lr0 * SROW + lc0], b0p + (k0));                 \
        cp_async16(&Bb[stage][lr1 * SROW + lc0], b1p + (k0));                 \
    } while (0)

    LOAD_TILE(0, 0);
    cp_commit();

    for (int tile = 0; tile < T; tile++) {
        if (tile + 1 < T) LOAD_TILE((tile + 1) & 1, (tile + 1) * 16);
        cp_commit();
        cp_wait1();
        __syncthreads();

        const float* as = Ab[tile & 1];
        const float* bs = Bb[tile & 1];

#pragma unroll
        for (int ks = 0; ks < 2; ks++) {
            uint32_t af[4][4];
#pragma unroll
            for (int mt = 0; mt < 4; mt++) {
                int m0 = wm * 64 + mt * 16;
                int kk = ks * 8 + tq;
                af[mt][0] = __float_as_uint(as[(m0 + g)     * SROW + kk]);
                af[mt][1] = __float_as_uint(as[(m0 + g + 8) * SROW + kk]);
                af[mt][2] = __float_as_uint(as[(m0 + g)     * SROW + kk + 4]);
                af[mt][3] = __float_as_uint(as[(m0 + g + 8) * SROW + kk + 4]);
            }
            uint32_t bf[4][2];
#pragma unroll
            for (int nt = 0; nt < 4; nt++) {
                int n0 = wn * 32 + nt * 8;
                int kk = ks * 8 + tq;
                bf[nt][0] = __float_as_uint(bs[(n0 + g) * SROW + kk]);
                bf[nt][1] = __float_as_uint(bs[(n0 + g) * SROW + kk + 4]);
            }
#pragma unroll
            for (int mt = 0; mt < 4; mt++)
#pragma unroll
                for (int nt = 0; nt < 4; nt++)
                    mma_tf32(acc[mt][nt], af[mt], bf[nt]);
        }
        __syncthreads();
    }
#undef LOAD_TILE

    // -------- stage accumulators (+bias) into smem tile Cs[128][CPAD] ------
    float* Cs = smem;
#pragma unroll
    for (int mt = 0; mt < 4; mt++) {
#pragma unroll
        for (int nt = 0; nt < 4; nt++) {
            int cl = wn * 32 + nt * 8 + 2 * tq;
            float bv0 = bias[nBase + cl], bv1 = bias[nBase + cl + 1];
#pragma unroll
            for (int half = 0; half < 2; half++) {
                int rl = wm * 64 + mt * 16 + g + half * 8;
                Cs[rl * CPAD + cl]     = acc[mt][nt][half * 2]     + bv0;
                Cs[rl * CPAD + cl + 1] = acc[mt][nt][half * 2 + 1] + bv1;
            }
        }
    }
    __syncthreads();

    // -------- coalesced writeback -----------------------------------------
    if (EPI == 4) {
        // head-major scatter: one 256B contiguous run per thread
        int li = t >> 7;            // 0/1 -> which l within tile
        int hh = (t >> 6) & 1;      // which 64-col half -> head
        int n  = t & 63;
        int row = mBase + li * 64 + n;
        if (row < M) {
            int l = row >> 6;
            int h = (nBase >> 6) + hh;
            float* dst = C + ((size_t)(n * Hh + h) * Lq + l) * HD;
            const float* src = Cs + (li * 64 + n) * CPAD + hh * 64;
#pragma unroll
            for (int k = 0; k < 16; k++)
                ((float4*)dst)[k] = *(const float4*)(src + k * 4);
        }
    } else {
        // row-major: full 512B row segments per warp
        for (int idx = t; idx < 128 * 32; idx += 256) {
            int r = idx >> 5, c4 = (idx & 31) << 2;
            int row = mBase + r;
            if (row >= M) continue;
            float4 v = *(const float4*)(Cs + r * CPAD + c4);
            size_t off = (size_t)row * Nc + nBase + c4;
            float4 rr = *(const float4*)(res + off);
            if (EPI == 2) {
                v.x += rr.x; v.y += rr.y; v.z += rr.z; v.w += rr.w;
            } else { // EPI == 3: quickGELU then residual
                v.x = rr.x + v.x / (1.0f + expf(-1.702f * v.x));
                v.y = rr.y + v.y / (1.0f + expf(-1.702f * v.y));
                v.z = rr.z + v.z / (1.0f + expf(-1.702f * v.z));
                v.w = rr.w + v.w / (1.0f + expf(-1.702f * v.w));
            }
            *(float4*)(C + off) = v;
        }
    }
}
#undef SROW

// ---------------- fused scores + softmax -----------------------------------
#define SK 65
#define SCORES_SMEM ((Lq * SK + 32 * SK) * 4)
__global__ void __launch_bounds__(256) scores_softmax(const float* __restrict__ Qh,
                                                      const float* __restrict__ Kh,
                                                      float* __restrict__ w) {
    extern __shared__ float sm[];
    float* Ks = sm;
    float* Qs = sm + Lq * SK;
    const int nh = blockIdx.y;
    const int lBase = blockIdx.x * 32;
    const int t = threadIdx.x;
    const int lane = t & 31, wid = t >> 5;

    {
        const float* kp = Kh + (size_t)nh * LHD;
        for (int idx = t; idx < Lq * 16; idx += 256) {
            int r = idx >> 4, c4 = (idx & 15) * 4;
            float4 v = *(const float4*)(kp + r * HD + c4);
            float* d = Ks + r * SK + c4;
            d[0] = v.x; d[1] = v.y; d[2] = v.z; d[3] = v.w;
        }
    }
    {
        const float* qp = Qh + (size_t)nh * LHD;
        for (int idx = t; idx < 32 * 16; idx += 256) {
            int r = idx >> 4, c4 = (idx & 15) * 4;
            int lg = lBase + r;
            float4 v = make_float4(0.f, 0.f, 0.f, 0.f);
            if (lg < Lq) v = *(const float4*)(qp + lg * HD + c4);
            float* d = Qs + r * SK + c4;
            d[0] = v.x; d[1] = v.y; d[2] = v.z; d[3] = v.w;
        }
    }
    __syncthreads();

    int moff[9];
#pragma unroll
    for (int j = 0; j < 9; j++) {
        int m = j * 32 + lane;
        moff[j] = (m < Lq ? m : Lq - 1) * SK;
    }

    float acc[4][9];
#pragma unroll
    for (int i = 0; i < 4; i++)
#pragma unroll
        for (int j = 0; j < 9; j++) acc[i][j] = 0.0f;

    const float* qbase = Qs + wid * 4 * SK;
#pragma unroll 4
    for (int hd = 0; hd < HD; hd++) {
        float q0 = qbase[hd];
        float q1 = qbase[SK + hd];
        float q2 = qbase[2 * SK + hd];
        float q3 = qbase[3 * SK + hd];
        float kk[9];
#pragma unroll
        for (int j = 0; j < 9; j++) kk[j] = Ks[moff[j] + hd];
#pragma unroll
        for (int j = 0; j < 9; j++) {
            acc[0][j] = fmaf(q0, kk[j], acc[0][j]);
            acc[1][j] = fmaf(q1, kk[j], acc[1][j]);
            acc[2][j] = fmaf(q2, kk[j], acc[2][j]);
            acc[3][j] = fmaf(q3, kk[j], acc[3][j]);
        }
    }

#pragma unroll
    for (int i = 0; i < 4; i++) {
        int row = lBase + wid * 4 + i;
        float mx = -INFINITY;
#pragma unroll
        for (int j = 0; j < 9; j++) {
            bool valid = (j * 32 + lane) < Lq;
            acc[i][j] = valid ? acc[i][j] * 0.125f : -INFINITY;
            mx = fmaxf(mx, acc[i][j]);
        }
#pragma unroll
        for (int off = 16; off > 0; off >>= 1)
            mx = fmaxf(mx, __shfl_xor_sync(0xffffffffu, mx, off));
        float s = 0.0f;
#pragma unroll
        for (int j = 0; j < 9; j++) {
            acc[i][j] = expf(acc[i][j] - mx);
            s += acc[i][j];
        }
#pragma unroll
        for (int off = 16; off > 0; off >>= 1)
            s += __shfl_xor_sync(0xffffffffu, s, off);
        float inv = 1.0f / s;
        if (row < Lq) {
            float* wr = w + ((size_t)nh * Lq + row) * Lq;
#pragma unroll
            for (int j = 0; j < 9; j++) {
                int m = j * 32 + lane;
                if (m < Lq) wr[m] = acc[i][j] * inv;
            }
        }
    }
}

// ---------------- attn = weights @ V (output pre-rounded tf32) -------------
#define SV 68
#define SW 260
#define ATTNV_SMEM ((Lq * SV + 32 * SW) * 4)
__global__ void __launch_bounds__(256) attnv2(const float* __restrict__ w,
                                              const float* __restrict__ Vh,
                                              float* __restrict__ out) {
    extern __shared__ float sm[];
    float* Vs = sm;
    float* Ws = sm + Lq * SV;
    const int nh = blockIdx.y;
    const int n = nh / Hh, h = nh % Hh;
    const int lBase = blockIdx.x * 32;
    const int t = threadIdx.x;

    {
        const float* vp = Vh + (size_t)nh * LHD;
        for (int idx = t; idx < Lq * 16; idx += 256) {
            int r = idx >> 4, c4 = (idx & 15) * 4;
            float4 v = *(const float4*)(vp + r * HD + c4);
            *(float4*)(Vs + r * SV + c4) = v;
        }
    }
    {
        for (int idx = t; idx < 32 * Lq; idx += 256) {
            int r = idx / Lq, c = idx - r * Lq;
            int lg = lBase + r;
            Ws[r * SW + c] = (lg < Lq)
                ? w[((size_t)nh * Lq + lg) * Lq + c] : 0.0f;
        }
    }
    __syncthreads();

    const int l = t >> 3;
    const int hb = (t & 7) * 8;
    const float* wrow = Ws + l * SW;

    float a0 = 0, a1 = 0, a2 = 0, a3 = 0, a4 = 0, a5 = 0, a6 = 0, a7 = 0;
#pragma unroll 4
    for (int m = 0; m < Lq; m++) {
        float wv = wrow[m];
        float4 v0 = *(const float4*)(Vs + m * SV + hb);
        float4 v1 = *(const float4*)(Vs + m * SV + hb + 4);
        a0 = fmaf(wv, v0.x, a0); a1 = fmaf(wv, v0.y, a1);
        a2 = fmaf(wv, v0.z, a2); a3 = fmaf(wv, v0.w, a3);
        a4 = fmaf(wv, v1.x, a4); a5 = fmaf(wv, v1.y, a5);
        a6 = fmaf(wv, v1.z, a6); a7 = fmaf(wv, v1.w, a7);
    }

    int lg = lBase + l;
    if (lg < Lq) {
        float* p = out + ((size_t)lg * Nb + n) * Dm + h * HD + hb;
        p[0] = round_tf32(a0); p[1] = round_tf32(a1);
        p[2] = round_tf32(a2); p[3] = round_tf32(a3);
        p[4] = round_tf32(a4); p[5] = round_tf32(a5);
        p[6] = round_tf32(a6); p[7] = round_tf32(a7);
    }
}

// ---------------------------------------------------------------------------
extern "C" void kernel_launch(void* const* d_in, const int* in_sizes, int n_in,
                              void* d_out, int out_size) {
    const float* x          = (const float*)d_in[0];
    const float* in_proj_w  = (const float*)d_in[1];
    const float* in_proj_b  = (const float*)d_in[2];
    const float* out_proj_w = (const float*)d_in[3];
    const float* out_proj_b = (const float*)d_in[4];
    const float* ln1_g      = (const float*)d_in[5];
    const float* ln1_b      = (const float*)d_in[6];
    const float* ln2_g      = (const float*)d_in[7];
    const float* ln2_b      = (const float*)d_in[8];
    const float* fc_w       = (const float*)d_in[9];
    const float* fc_b       = (const float*)d_in[10];

    float* out_x = (float*)d_out;
    float* out_w = (float*)d_out + X_ELEMS;

    cudaFuncSetAttribute(gemm_tc<2>, cudaFuncAttributeMaxDynamicSharedMemorySize, GEMM_SMEM_BYTES);
    cudaFuncSetAttribute(gemm_tc<3>, cudaFuncAttributeMaxDynamicSharedMemorySize, GEMM_SMEM_BYTES);
    cudaFuncSetAttribute(gemm_tc<4>, cudaFuncAttributeMaxDynamicSharedMemorySize, GEMM_SMEM_BYTES);
    cudaFuncSetAttribute(scores_softmax, cudaFuncAttributeMaxDynamicSharedMemorySize, SCORES_SMEM);
    cudaFuncSetAttribute(attnv2,         cudaFuncAttributeMaxDynamicSharedMemorySize, ATTNV_SMEM);

    float* h    = g_h;
    float* qkvh = g_qkv;
    float* attn = g_attn;
    float* x1   = g_x1;
    float* w_in = g_w_in;
    float* w_out= g_w_out;
    float* w_fc = g_w_fc;

    const int mGrid = (Mrows + 127) / 128;   // 129
    const int lGrid = (Lq + 31) / 32;        // 9
    dim3 ggrid(Dm / 128, mGrid);             // (6, 129) for all GEMMs

    // 1) LN1 (h pre-rounded to tf32)
    ln_kernel<<<Mrows, 256>>>(x, ln1_g, ln1_b, h);

    // 2-3) pre-round in_proj / out_proj weights to tf32
    {
        int n4 = (D3 * Dm) / 4;
        round_w<<<(n4 + 255) / 256, 256>>>(in_proj_w, w_in, n4);
        n4 = (Dm * Dm) / 4;
        round_w<<<(n4 + 255) / 256, 256>>>(out_proj_w, w_out, n4);
    }

    // 4-6) qkv slices: Q, K, V  (4th launch = gemmQ -> gets profiled)
    for (int which = 0; which < 3; which++) {
        gemm_tc<4><<<ggrid, 256, GEMM_SMEM_BYTES>>>(
            h, w_in + (size_t)which * Dm * Dm, in_proj_b + which * Dm,
            nullptr, qkvh + (size_t)which * X_ELEMS, Dm, Dm, Mrows);
    }

    // 7) fused scores + softmax -> weights output
    {
        dim3 grid(lGrid, NH);
        scores_softmax<<<grid, 256, SCORES_SMEM>>>(qkvh, qkvh + X_ELEMS, out_w);
    }

    // 8) attn = weights @ V (rounded tf32 out)
    {
        dim3 grid(lGrid, NH);
        attnv2<<<grid, 256, ATTNV_SMEM>>>(out_w, qkvh + 2 * X_ELEMS, attn);
    }

    // 9) x1 = x + attn @ W_out^T + b
    gemm_tc<2><<<ggrid, 256, GEMM_SMEM_BYTES>>>(attn, w_out, out_proj_b, x, x1, Dm, Dm, Mrows);

    // 10) LN2 (h pre-rounded)
    ln_kernel<<<Mrows, 256>>>(x1, ln2_g, ln2_b, h);

    // 11) pre-round fc weights
    {
        int n4 = (Dm * Dm) / 4;
        round_w<<<(n4 + 255) / 256, 256>>>(fc_w, w_fc, n4);
    }

    // 12) out = x1 + quick_gelu(h @ fc_w^T + fc_b)
    gemm_tc<3><<<ggrid, 256, GEMM_SMEM_BYTES>>>(h, w_fc, fc_b, x1, out_x, Dm, Dm, Mrows);
}

// round 12
// speedup vs baseline: 9.2702x; 9.2702x over previous
#include <cuda_runtime.h>
#include <math.h>
#include <stdint.h>

#define Lq 257
#define Nb 64
#define Dm 768
#define Hh 12
#define HD 64
#define NH (Nb * Hh)               // 768
#define Mrows (Lq * Nb)            // 16448
#define D3 (3 * Dm)                // 2304
#define LHD (Lq * HD)
#define X_ELEMS ((size_t)Mrows * Dm)

#define NBLK 148                   // persistent grid: 1 CTA/SM guaranteed
#define NUM_BAR 6

// ---------------- scratch (device globals; no allocation allowed) ----------
__device__ float g_h[Mrows * Dm];
__device__ float g_qkv[(size_t)Mrows * D3];   // head-major [which][nh][l][hd]
__device__ float g_attn[Mrows * Dm];
__device__ float g_x1[Mrows * Dm];
__device__ unsigned g_bar[NUM_BAR];           // zero-init; ring-reset keeps invariant

// ---------------- PTX helpers ----------------------------------------------
__device__ __forceinline__ uint32_t f2tf(float f) {
    uint32_t r;
    asm("cvt.rna.tf32.f32 %0, %1;" : "=r"(r) : "f"(f));
    return r;
}
__device__ __forceinline__ void mma_tf32(float* c, const uint32_t* a, const uint32_t* b) {
    asm volatile(
        "mma.sync.aligned.m16n8k8.row.col.f32.tf32.tf32.f32 "
        "{%0,%1,%2,%3}, {%4,%5,%6,%7}, {%8,%9}, {%0,%1,%2,%3};\n"
        : "+f"(c[0]), "+f"(c[1]), "+f"(c[2]), "+f"(c[3])
        : "r"(a[0]), "r"(a[1]), "r"(a[2]), "r"(a[3]), "r"(b[0]), "r"(b[1]));
}
__device__ __forceinline__ void cp_async16(void* smem, const void* gmem) {
    uint32_t s = (uint32_t)__cvta_generic_to_shared(smem);
    asm volatile("cp.async.ca.shared.global [%0], [%1], 16;\n" :: "r"(s), "l"(gmem));
}
__device__ __forceinline__ void cp_commit() { asm volatile("cp.async.commit_group;\n"); }
__device__ __forceinline__ void cp_wait1()  { asm volatile("cp.async.wait_group 1;\n"); }
__device__ __forceinline__ void cp_wait0()  { asm volatile("cp.async.wait_group 0;\n"); }

// ---------------- software grid barrier (replay-safe ring) ------------------
__device__ __forceinline__ void grid_bar(int k) {
    __threadfence();
    __syncthreads();
    if (threadIdx.x == 0) {
        unsigned prev = atomicAdd(&g_bar[k], 1u);
        if (prev == NBLK - 1) {
            int km1 = (k + NUM_BAR - 1) % NUM_BAR;
            atomicExch(&g_bar[km1], 0u);   // all blocks already passed km1
        }
        unsigned v;
        do {
            asm volatile("ld.acquire.gpu.u32 %0, [%1];" : "=r"(v) : "l"(&g_bar[k]) : "memory");
        } while (v < NBLK);
    }
    __syncthreads();
}

// ---------------- phase: LayerNorm (block-stride rows) ----------------------
__device__ void ln_phase(const float* __restrict__ x,
                         const float* __restrict__ g,
                         const float* __restrict__ b,
                         float* __restrict__ out) {
    __shared__ float red[256];
    int tid = threadIdx.x;
    for (int row = blockIdx.x; row < Mrows; row += NBLK) {
        const float* xr = x + (size_t)row * Dm;
        float v0 = xr[tid], v1 = xr[tid + 256], v2 = xr[tid + 512];

        red[tid] = v0 + v1 + v2; __syncthreads();
        for (int off = 128; off > 0; off >>= 1) {
            if (tid < off) red[tid] += red[tid + off];
            __syncthreads();
        }
        float mu = red[0] * (1.0f / Dm);
        __syncthreads();

        float d0 = v0 - mu, d1 = v1 - mu, d2 = v2 - mu;
        red[tid] = d0 * d0 + d1 * d1 + d2 * d2; __syncthreads();
        for (int off = 128; off > 0; off >>= 1) {
            if (tid < off) red[tid] += red[tid + off];
            __syncthreads();
        }
        float rstd = rsqrtf(red[0] * (1.0f / Dm) + 1e-5f);
        __syncthreads();

        float* orow = out + (size_t)row * Dm;
        orow[tid]       = d0 * rstd * g[tid]       + b[tid];
        orow[tid + 256] = d1 * rstd * g[tid + 256] + b[tid + 256];
        orow[tid + 512] = d2 * rstd * g[tid + 512] + b[tid + 512];
    }
}

// ---------------- phase: TF32 MMA GEMM NT, K=768 ----------------------------
// C[M,Nc] = A[M,768] * B[Nc,768]^T. BM=BN=128, BK=16, 8 warps.
// epi: 2 = +bias+res, 3 = res + quickGELU(C+bias), 4 = +bias, head-major scatter
#define SROW 20
#define CPAD 132
__device__ void gemm_phase(const float* __restrict__ A,
                           const float* __restrict__ B,
                           const float* __restrict__ bias,
                           const float* __restrict__ res,
                           float* __restrict__ C,
                           int nTilesX, int nTiles, int epi,
                           float* smem) {
    float* Ab[2] = { smem,        smem + 2560 };
    float* Bb[2] = { smem + 5120, smem + 7680 };
    float* Cs = smem;

    const int t = threadIdx.x;
    const int wid = t >> 5, lane = t & 31;
    const int wm = wid >> 2, wn = wid & 3;
    const int g = lane >> 2, tq = lane & 3;
    const int lr0 = t >> 2, lc0 = (t & 3) * 4;
    const int lr1 = lr0 + 64;
    const int Nc = nTilesX * 128;

    for (int tile = blockIdx.x; tile < nTiles; tile += NBLK) {
        const int bx = tile % nTilesX, by = tile / nTilesX;
        const int mBase = by * 128, nBase = bx * 128;

        float acc[4][4][4];
#pragma unroll
        for (int i = 0; i < 4; i++)
#pragma unroll
            for (int j = 0; j < 4; j++)
#pragma unroll
                for (int q = 0; q < 4; q++) acc[i][j][q] = 0.0f;

        int arow0 = mBase + lr0; if (arow0 >= Mrows) arow0 = Mrows - 1;
        int arow1 = mBase + lr1; if (arow1 >= Mrows) arow1 = Mrows - 1;
        const float* a0p = A + (size_t)arow0 * Dm + lc0;
        const float* a1p = A + (size_t)arow1 * Dm + lc0;
        const float* b0p = B + (size_t)(nBase + lr0) * Dm + lc0;
        const float* b1p = B + (size_t)(nBase + lr1) * Dm + lc0;

#define LOAD_TILE(stage, k0)                                              \
        do {                                                              \
            cp_async16(&Ab[stage][lr0 * SROW + lc0], a0p + (k0));         \
            cp_async16(&Ab[stage][lr1 * SROW + lc0], a1p + (k0));         \
            cp_async16(&Bb[stage][lr0 * SROW + lc0], b0p + (k0));         \
            cp_async16(&Bb[stage][lr1 * SROW + lc0], b1p + (k0));         \
        } while (0)

        LOAD_TILE(0, 0);
        cp_commit();

        const int T = Dm / 16;   // 48
        for (int kt = 0; kt < T; kt++) {
            if (kt + 1 < T) LOAD_TILE((kt + 1) & 1, (kt + 1) * 16);
            cp_commit();
            cp_wait1();
            __syncthreads();

            const float* as = Ab[kt & 1];
            const float* bs = Bb[kt & 1];
#pragma unroll
            for (int ks = 0; ks < 2; ks++) {
                uint32_t af[4][4];
#pragma unroll
                for (int mt = 0; mt < 4; mt++) {
                    int m0 = wm * 64 + mt * 16;
                    int kk = ks * 8 + tq;
                    af[mt][0] = f2tf(as[(m0 + g)     * SROW + kk]);
                    af[mt][1] = f2tf(as[(m0 + g + 8) * SROW + kk]);
                    af[mt][2] = f2tf(as[(m0 + g)     * SROW + kk + 4]);
                    af[mt][3] = f2tf(as[(m0 + g + 8) * SROW + kk + 4]);
                }
                uint32_t bf[4][2];
#pragma unroll
                for (int nt = 0; nt < 4; nt++) {
                    int n0 = wn * 32 + nt * 8;
                    int kk = ks * 8 + tq;
                    bf[nt][0] = f2tf(bs[(n0 + g) * SROW + kk]);
                    bf[nt][1] = f2tf(bs[(n0 + g) * SROW + kk + 4]);
                }
#pragma unroll
                for (int mt = 0; mt < 4; mt++)
#pragma unroll
                    for (int nt = 0; nt < 4; nt++)
                        mma_tf32(acc[mt][nt], af[mt], bf[nt]);
            }
            __syncthreads();
        }
#undef LOAD_TILE
        cp_wait0();

        // stage accumulators (+bias) into Cs[128][CPAD]
#pragma unroll
        for (int mt = 0; mt < 4; mt++) {
#pragma unroll
            for (int nt = 0; nt < 4; nt++) {
                int cl = wn * 32 + nt * 8 + 2 * tq;
                float bv0 = bias[nBase + cl], bv1 = bias[nBase + cl + 1];
#pragma unroll
                for (int half = 0; half < 2; half++) {
                    int rl = wm * 64 + mt * 16 + g + half * 8;
                    Cs[rl * CPAD + cl]     = acc[mt][nt][half * 2]     + bv0;
                    Cs[rl * CPAD + cl + 1] = acc[mt][nt][half * 2 + 1] + bv1;
                }
            }
        }
        __syncthreads();

        if (epi == 4) {
            // head-major scatter: 256B contiguous run per thread
            int li = t >> 7, hh = (t >> 6) & 1, n = t & 63;
            int row = mBase + li * 64 + n;
            if (row < Mrows) {
                int l = row >> 6;
                int c0 = nBase + hh * 64;
                int which = c0 / Dm;
                int h = (c0 - which * Dm) >> 6;
                float* dst = C + ((size_t)which * X_ELEMS)
                           + ((size_t)(n * Hh + h) * Lq + l) * HD;
                const float* src = Cs + (li * 64 + n) * CPAD + hh * 64;
#pragma unroll
                for (int k4 = 0; k4 < 16; k4++)
                    ((float4*)dst)[k4] = *(const float4*)(src + k4 * 4);
            }
        } else {
            for (int idx = t; idx < 128 * 32; idx += 256) {
                int r = idx >> 5, c4 = (idx & 31) << 2;
                int row = mBase + r;
                if (row >= Mrows) continue;
                float4 v = *(const float4*)(Cs + r * CPAD + c4);
                size_t off = (size_t)row * Nc + nBase + c4;
                float4 rr = *(const float4*)(res + off);
                if (epi == 2) {
                    v.x += rr.x; v.y += rr.y; v.z += rr.z; v.w += rr.w;
                } else {
                    v.x = rr.x + v.x / (1.0f + expf(-1.702f * v.x));
                    v.y = rr.y + v.y / (1.0f + expf(-1.702f * v.y));
                    v.z = rr.z + v.z / (1.0f + expf(-1.702f * v.z));
                    v.w = rr.w + v.w / (1.0f + expf(-1.702f * v.w));
                }
                *(float4*)(C + off) = v;
            }
        }
        __syncthreads();   // Cs aliases Ab/Bb of next tile
    }
}

// ---------------- phase: fused scores + softmax ------------------------------
#define SK 65
__device__ void scores_phase(const float* __restrict__ Qh,
                             const float* __restrict__ Kh,
                             float* __restrict__ w,
                             float* smem) {
    float* Ks = smem;
    float* Qs = smem + Lq * SK;
    const int t = threadIdx.x;
    const int lane = t & 31, wid = t >> 5;

    for (int u = blockIdx.x; u < 9 * NH; u += NBLK) {
        const int nh = u / 9;
        const int lBase = (u - nh * 9) * 32;

        {
            const float* kp = Kh + (size_t)nh * LHD;
            for (int idx = t; idx < Lq * 16; idx += 256) {
                int r = idx >> 4, c4 = (idx & 15) * 4;
                float4 v = *(const float4*)(kp + r * HD + c4);
                float* d = Ks + r * SK + c4;
                d[0] = v.x; d[1] = v.y; d[2] = v.z; d[3] = v.w;
            }
            const float* qp = Qh + (size_t)nh * LHD;
            for (int idx = t; idx < 32 * 16; idx += 256) {
                int r = idx >> 4, c4 = (idx & 15) * 4;
                int lg = lBase + r;
                float4 v = make_float4(0.f, 0.f, 0.f, 0.f);
                if (lg < Lq) v = *(const float4*)(qp + lg * HD + c4);
                float* d = Qs + r * SK + c4;
                d[0] = v.x; d[1] = v.y; d[2] = v.z; d[3] = v.w;
            }
        }
        __syncthreads();

        int moff[9];
#pragma unroll
        for (int j = 0; j < 9; j++) {
            int m = j * 32 + lane;
            moff[j] = (m < Lq ? m : Lq - 1) * SK;
        }

        float acc[4][9];
#pragma unroll
        for (int i = 0; i < 4; i++)
#pragma unroll
            for (int j = 0; j < 9; j++) acc[i][j] = 0.0f;

        const float* qbase = Qs + wid * 4 * SK;
#pragma unroll 4
        for (int hd = 0; hd < HD; hd++) {
            float q0 = qbase[hd];
            float q1 = qbase[SK + hd];
            float q2 = qbase[2 * SK + hd];
            float q3 = qbase[3 * SK + hd];
            float kk[9];
#pragma unroll
            for (int j = 0; j < 9; j++) kk[j] = Ks[moff[j] + hd];
#pragma unroll
            for (int j = 0; j < 9; j++) {
                acc[0][j] = fmaf(q0, kk[j], acc[0][j]);
                acc[1][j] = fmaf(q1, kk[j], acc[1][j]);
                acc[2][j] = fmaf(q2, kk[j], acc[2][j]);
                acc[3][j] = fmaf(q3, kk[j], acc[3][j]);
            }
        }

#pragma unroll
        for (int i = 0; i < 4; i++) {
            int row = lBase + wid * 4 + i;
            float mx = -INFINITY;
#pragma unroll
            for (int j = 0; j < 9; j++) {
                bool valid = (j * 32 + lane) < Lq;
                acc[i][j] = valid ? acc[i][j] * 0.125f : -INFINITY;
                mx = fmaxf(mx, acc[i][j]);
            }
#pragma unroll
            for (int off = 16; off > 0; off >>= 1)
                mx = fmaxf(mx, __shfl_xor_sync(0xffffffffu, mx, off));
            float s = 0.0f;
#pragma unroll
            for (int j = 0; j < 9; j++) {
                acc[i][j] = expf(acc[i][j] - mx);
                s += acc[i][j];
            }
#pragma unroll
            for (int off = 16; off > 0; off >>= 1)
                s += __shfl_xor_sync(0xffffffffu, s, off);
            float inv = 1.0f / s;
            if (row < Lq) {
                float* wr = w + ((size_t)nh * Lq + row) * Lq;
#pragma unroll
                for (int j = 0; j < 9; j++) {
                    int m = j * 32 + lane;
                    if (m < Lq) wr[m] = acc[i][j] * inv;
                }
            }
        }
        __syncthreads();   // before next unit overwrites Ks/Qs
    }
}

// ---------------- phase: attn = weights @ V ----------------------------------
#define SV 68
#define SW 260
__device__ void attnv_phase(const float* __restrict__ w,
                            const float* __restrict__ Vh,
                            float* __restrict__ out,
                            float* smem) {
    float* Vs = smem;
    float* Ws = smem + Lq * SV;
    const int t = threadIdx.x;

    for (int u = blockIdx.x; u < 9 * NH; u += NBLK) {
        const int nh = u / 9;
        const int lBase = (u - nh * 9) * 32;
        const int n = nh / Hh, h = nh - n * Hh;

        {
            const float* vp = Vh + (size_t)nh * LHD;
            for (int idx = t; idx < Lq * 16; idx += 256) {
                int r = idx >> 4, c4 = (idx & 15) * 4;
                float4 v = *(const float4*)(vp + r * HD + c4);
                *(float4*)(Vs + r * SV + c4) = v;
            }
            for (int idx = t; idx < 32 * Lq; idx += 256) {
                int r = idx / Lq, c = idx - r * Lq;
                int lg = lBase + r;
                Ws[r * SW + c] = (lg < Lq)
                    ? w[((size_t)nh * Lq + lg) * Lq + c] : 0.0f;
            }
        }
        __syncthreads();

        const int l = t >> 3;
        const int hb = (t & 7) * 8;
        const float* wrow = Ws + l * SW;

        float a0 = 0, a1 = 0, a2 = 0, a3 = 0, a4 = 0, a5 = 0, a6 = 0, a7 = 0;
#pragma unroll 4
        for (int m = 0; m < Lq; m++) {
            float wv = wrow[m];
            float4 v0 = *(const float4*)(Vs + m * SV + hb);
            float4 v1 = *(const float4*)(Vs + m * SV + hb + 4);
            a0 = fmaf(wv, v0.x, a0); a1 = fmaf(wv, v0.y, a1);
            a2 = fmaf(wv, v0.z, a2); a3 = fmaf(wv, v0.w, a3);
            a4 = fmaf(wv, v1.x, a4); a5 = fmaf(wv, v1.y, a5);
            a6 = fmaf(wv, v1.z, a6); a7 = fmaf(wv, v1.w, a7);
        }

        int lg = lBase + l;
        if (lg < Lq) {
            float* p = out + ((size_t)lg * Nb + n) * Dm + h * HD + hb;
            p[0] = a0; p[1] = a1; p[2] = a2; p[3] = a3;
            p[4] = a4; p[5] = a5; p[6] = a6; p[7] = a7;
        }
        __syncthreads();
    }
}

// ---------------- the single fused kernel ------------------------------------
#define DSMEM_BYTES ((Lq * SV + 32 * SW) * 4)   // 103,184 B (max over phases)

__global__ void __launch_bounds__(256, 1)
fused_block(const float* __restrict__ x,
            const float* __restrict__ in_proj_w,
            const float* __restrict__ in_proj_b,
            const float* __restrict__ out_proj_w,
            const float* __restrict__ out_proj_b,
            const float* __restrict__ ln1_g, const float* __restrict__ ln1_b,
            const float* __restrict__ ln2_g, const float* __restrict__ ln2_b,
            const float* __restrict__ fc_w,  const float* __restrict__ fc_b,
            float* __restrict__ out_x, float* __restrict__ out_w) {
    extern __shared__ float dsm[];

    // 1) LN1: x -> g_h
    ln_phase(x, ln1_g, ln1_b, g_h);
    grid_bar(0);

    // 2) qkv = g_h @ in_proj_w^T + b  -> head-major g_qkv
    gemm_phase(g_h, in_proj_w, in_proj_b, nullptr, g_qkv,
               D3 / 128, (D3 / 128) * 129, 4, dsm);
    grid_bar(1);

    // 3) fused scores + softmax -> out_w (final weights)
    scores_phase(g_qkv, g_qkv + X_ELEMS, out_w, dsm);
    grid_bar(2);

    // 4) attn = weights @ V -> g_attn
    attnv_phase(out_w, g_qkv + 2 * X_ELEMS, g_attn, dsm);
    grid_bar(3);

    // 5) x1 = x + attn @ out_proj_w^T + b
    gemm_phase(g_attn, out_proj_w, out_proj_b, x, g_x1,
               Dm / 128, (Dm / 128) * 129, 2, dsm);
    grid_bar(4);

    // 6) LN2: x1 -> g_h
    ln_phase(g_x1, ln2_g, ln2_b, g_h);
    grid_bar(5);

    // 7) out_x = x1 + quickGELU(g_h @ fc_w^T + fc_b)
    gemm_phase(g_h, fc_w, fc_b, g_x1, out_x,
               Dm / 128, (Dm / 128) * 129, 3, dsm);
}

// ---------------------------------------------------------------------------
extern "C" void kernel_launch(void* const* d_in, const int* in_sizes, int n_in,
                              void* d_out, int out_size) {
    const float* x          = (const float*)d_in[0];
    const float* in_proj_w  = (const float*)d_in[1];
    const float* in_proj_b  = (const float*)d_in[2];
    const float* out_proj_w = (const float*)d_in[3];
    const float* out_proj_b = (const float*)d_in[4];
    const float* ln1_g      = (const float*)d_in[5];
    const float* ln1_b      = (const float*)d_in[6];
    const float* ln2_g      = (const float*)d_in[7];
    const float* ln2_b      = (const float*)d_in[8];
    const float* fc_w       = (const float*)d_in[9];
    const float* fc_b       = (const float*)d_in[10];

    float* out_x = (float*)d_out;
    float* out_w = (float*)d_out + X_ELEMS;

    static int configured = 0;
    if (!configured) {
        cudaFuncSetAttribute(fused_block,
                             cudaFuncAttributeMaxDynamicSharedMemorySize,
                             DSMEM_BYTES);
        configured = 1;
    }

    fused_block<<<NBLK, 256, DSMEM_BYTES>>>(
        x, in_proj_w, in_proj_b, out_proj_w, out_proj_b,
        ln1_g, ln1_b, ln2_g, ln2_b, fc_w, fc_b, out_x, out_w);
}

// round 14
// speedup vs baseline: 11.9055x; 1.2843x over previous
#include <cuda_runtime.h>
#include <math.h>
#include <stdint.h>

#define Lq 257
#define Nb 64
#define Dm 768
#define Hh 12
#define HD 64
#define NH (Nb * Hh)               // 768
#define Mrows (Lq * Nb)            // 16448
#define D3 (3 * Dm)                // 2304
#define LHD (Lq * HD)
#define X_ELEMS ((size_t)Mrows * Dm)

#define NBLK 148                   // persistent grid: 1 CTA/SM
#define NTHR 512                   // 16 warps
#define NUM_BAR 6

// ---------------- scratch (device globals; no allocation allowed) ----------
__device__ float g_h[Mrows * Dm];
__device__ float g_qkv[(size_t)Mrows * D3];   // head-major [which][nh][l][hd]
__device__ float g_attn[Mrows * Dm];
__device__ float g_x1[Mrows * Dm];
__device__ unsigned g_bar[NUM_BAR];

// ---------------- PTX helpers ----------------------------------------------
__device__ __forceinline__ uint32_t f2tf(float f) {
    uint32_t r;
    asm("cvt.rna.tf32.f32 %0, %1;" : "=r"(r) : "f"(f));
    return r;
}
__device__ __forceinline__ void mma_tf32(float* c, const uint32_t* a, const uint32_t* b) {
    asm volatile(
        "mma.sync.aligned.m16n8k8.row.col.f32.tf32.tf32.f32 "
        "{%0,%1,%2,%3}, {%4,%5,%6,%7}, {%8,%9}, {%0,%1,%2,%3};\n"
        : "+f"(c[0]), "+f"(c[1]), "+f"(c[2]), "+f"(c[3])
        : "r"(a[0]), "r"(a[1]), "r"(a[2]), "r"(a[3]), "r"(b[0]), "r"(b[1]));
}
__device__ __forceinline__ void cp_async16(void* smem, const void* gmem) {
    uint32_t s = (uint32_t)__cvta_generic_to_shared(smem);
    asm volatile("cp.async.ca.shared.global [%0], [%1], 16;\n" :: "r"(s), "l"(gmem));
}
__device__ __forceinline__ void cp_commit() { asm volatile("cp.async.commit_group;\n"); }
__device__ __forceinline__ void cp_wait1()  { asm volatile("cp.async.wait_group 1;\n"); }
__device__ __forceinline__ void cp_wait0()  { asm volatile("cp.async.wait_group 0;\n"); }

// ---------------- software grid barrier (replay-safe ring) ------------------
__device__ __forceinline__ void grid_bar(int k) {
    __threadfence();
    __syncthreads();
    if (threadIdx.x == 0) {
        unsigned prev = atomicAdd(&g_bar[k], 1u);
        if (prev == NBLK - 1) {
            int km1 = (k + NUM_BAR - 1) % NUM_BAR;
            atomicExch(&g_bar[km1], 0u);
        }
        unsigned v;
        do {
            asm volatile("ld.acquire.gpu.u32 %0, [%1];" : "=r"(v) : "l"(&g_bar[k]) : "memory");
        } while (v < NBLK);
    }
    __syncthreads();
}

// ---------------- phase: LayerNorm, warp-per-row -----------------------------
__device__ void ln_phase(const float* __restrict__ x,
                         const float* __restrict__ g,
                         const float* __restrict__ b,
                         float* __restrict__ out) {
    const int t = threadIdx.x;
    const int wid = t >> 5, lane = t & 31;
    for (int row = blockIdx.x * 16 + wid; row < Mrows; row += NBLK * 16) {
        const float* xr = x + (size_t)row * Dm;
        float v[24];
        float s = 0.0f;
#pragma unroll
        for (int k = 0; k < 24; k++) { v[k] = xr[lane + k * 32]; s += v[k]; }
#pragma unroll
        for (int off = 16; off > 0; off >>= 1)
            s += __shfl_xor_sync(0xffffffffu, s, off);
        float mu = s * (1.0f / Dm);

        float sq = 0.0f;
#pragma unroll
        for (int k = 0; k < 24; k++) { float d = v[k] - mu; sq += d * d; }
#pragma unroll
        for (int off = 16; off > 0; off >>= 1)
            sq += __shfl_xor_sync(0xffffffffu, sq, off);
        float rstd = rsqrtf(sq * (1.0f / Dm) + 1e-5f);

        float* orow = out + (size_t)row * Dm;
#pragma unroll
        for (int k = 0; k < 24; k++) {
            int idx = lane + k * 32;
            orow[idx] = (v[k] - mu) * rstd * g[idx] + b[idx];
        }
    }
}

// ---------------- phase: TF32 MMA GEMM NT, K=768 -----------------------------
// BM=BN=128, BK=16, 16 warps in 4x4 grid, warp tile 32x32.
// epi: 2 = +bias+res, 3 = res + quickGELU(C+bias), 4 = +bias, head-major scatter
#define SROW 20
#define CPAD 132
__device__ void gemm_phase(const float* __restrict__ A,
                           const float* __restrict__ B,
                           const float* __restrict__ bias,
                           const float* __restrict__ res,
                           float* __restrict__ C,
                           int nTilesX, int nTiles, int epi,
                           float* smem) {
    float* Ab[2] = { smem,        smem + 2560 };
    float* Bb[2] = { smem + 5120, smem + 7680 };
    float* Cs = smem;

    const int t = threadIdx.x;
    const int wid = t >> 5, lane = t & 31;
    const int wm = wid >> 2, wn = wid & 3;        // 4 x 4 warp grid
    const int g = lane >> 2, tq = lane & 3;
    const int lr = t >> 2, lc = (t & 3) * 4;      // 128 rows x 16 cols loaders
    const int Nc = nTilesX * 128;

    for (int tile = blockIdx.x; tile < nTiles; tile += NBLK) {
        const int bx = tile % nTilesX, by = tile / nTilesX;
        const int mBase = by * 128, nBase = bx * 128;

        float acc[2][4][4];
#pragma unroll
        for (int i = 0; i < 2; i++)
#pragma unroll
            for (int j = 0; j < 4; j++)
#pragma unroll
                for (int q = 0; q < 4; q++) acc[i][j][q] = 0.0f;

        int arow = mBase + lr; if (arow >= Mrows) arow = Mrows - 1;
        const float* ap = A + (size_t)arow * Dm + lc;
        const float* bp = B + (size_t)(nBase + lr) * Dm + lc;

#define LOAD_TILE(stage, k0)                                              \
        do {                                                              \
            cp_async16(&Ab[stage][lr * SROW + lc], ap + (k0));            \
            cp_async16(&Bb[stage][lr * SROW + lc], bp + (k0));            \
        } while (0)

        LOAD_TILE(0, 0);
        cp_commit();

        const int T = Dm / 16;   // 48
        for (int kt = 0; kt < T; kt++) {
            if (kt + 1 < T) LOAD_TILE((kt + 1) & 1, (kt + 1) * 16);
            cp_commit();
            cp_wait1();
            __syncthreads();

            const float* as = Ab[kt & 1];
            const float* bs = Bb[kt & 1];
#pragma unroll
            for (int ks = 0; ks < 2; ks++) {
                const int kk = ks * 8 + tq;
                uint32_t af[2][4];
#pragma unroll
                for (int mt = 0; mt < 2; mt++) {
                    int m0 = wm * 32 + mt * 16;
                    af[mt][0] = f2tf(as[(m0 + g)     * SROW + kk]);
                    af[mt][1] = f2tf(as[(m0 + g + 8) * SROW + kk]);
                    af[mt][2] = f2tf(as[(m0 + g)     * SROW + kk + 4]);
                    af[mt][3] = f2tf(as[(m0 + g + 8) * SROW + kk + 4]);
                }
                uint32_t bf[4][2];
#pragma unroll
                for (int nt = 0; nt < 4; nt++) {
                    int n0 = wn * 32 + nt * 8;
                    bf[nt][0] = f2tf(bs[(n0 + g) * SROW + kk]);
                    bf[nt][1] = f2tf(bs[(n0 + g) * SROW + kk + 4]);
                }
#pragma unroll
                for (int mt = 0; mt < 2; mt++)
#pragma unroll
                    for (int nt = 0; nt < 4; nt++)
                        mma_tf32(acc[mt][nt], af[mt], bf[nt]);
            }
            __syncthreads();
        }
#undef LOAD_TILE
        cp_wait0();

        // stage accumulators (+bias) into Cs[128][CPAD]
#pragma unroll
        for (int mt = 0; mt < 2; mt++) {
#pragma unroll
            for (int nt = 0; nt < 4; nt++) {
                int cl = wn * 32 + nt * 8 + 2 * tq;
                float bv0 = bias[nBase + cl], bv1 = bias[nBase + cl + 1];
#pragma unroll
                for (int half = 0; half < 2; half++) {
                    int rl = wm * 32 + mt * 16 + g + half * 8;
                    Cs[rl * CPAD + cl]     = acc[mt][nt][half * 2]     + bv0;
                    Cs[rl * CPAD + cl + 1] = acc[mt][nt][half * 2 + 1] + bv1;
                }
            }
        }
        __syncthreads();

        if (epi == 4) {
            // head-major scatter: each thread 32 contiguous floats (128 B)
            int rloc = t & 127;          // local row
            int q    = t >> 7;           // 0..3 -> 32-col quarter
            int row = mBase + rloc;
            if (row < Mrows) {
                int l = row >> 6, n = row & 63;
                int c0 = nBase + (q >> 1) * 64;
                int which = c0 / Dm;
                int h = (c0 - which * Dm) >> 6;
                float* dst = C + ((size_t)which * X_ELEMS)
                           + ((size_t)(n * Hh + h) * Lq + l) * HD + (q & 1) * 32;
                const float* src = Cs + rloc * CPAD + (q >> 1) * 64 + (q & 1) * 32;
#pragma unroll
                for (int k4 = 0; k4 < 8; k4++)
                    ((float4*)dst)[k4] = *(const float4*)(src + k4 * 4);
            }
        } else {
            for (int idx = t; idx < 128 * 32; idx += NTHR) {
                int r = idx >> 5, c4 = (idx & 31) << 2;
                int row = mBase + r;
                if (row >= Mrows) continue;
                float4 v = *(const float4*)(Cs + r * CPAD + c4);
                size_t off = (size_t)row * Nc + nBase + c4;
                float4 rr = *(const float4*)(res + off);
                if (epi == 2) {
                    v.x += rr.x; v.y += rr.y; v.z += rr.z; v.w += rr.w;
                } else {
                    v.x = rr.x + v.x / (1.0f + expf(-1.702f * v.x));
                    v.y = rr.y + v.y / (1.0f + expf(-1.702f * v.y));
                    v.z = rr.z + v.z / (1.0f + expf(-1.702f * v.z));
                    v.w = rr.w + v.w / (1.0f + expf(-1.702f * v.w));
                }
                *(float4*)(C + off) = v;
            }
        }
        __syncthreads();
    }
}

// ---------------- phase: fused scores + softmax ------------------------------
#define SK 65
__device__ void scores_phase(const float* __restrict__ Qh,
                             const float* __restrict__ Kh,
                             float* __restrict__ w,
                             float* smem) {
    float* Ks = smem;
    float* Qs = smem + Lq * SK;
    const int t = threadIdx.x;
    const int lane = t & 31, wid = t >> 5;

    for (int u = blockIdx.x; u < 9 * NH; u += NBLK) {
        const int nh = u / 9;
        const int lBase = (u - nh * 9) * 32;

        {
            const float* kp = Kh + (size_t)nh * LHD;
            for (int idx = t; idx < Lq * 16; idx += NTHR) {
                int r = idx >> 4, c4 = (idx & 15) * 4;
                float4 v = *(const float4*)(kp + r * HD + c4);
                float* d = Ks + r * SK + c4;
                d[0] = v.x; d[1] = v.y; d[2] = v.z; d[3] = v.w;
            }
            const float* qp = Qh + (size_t)nh * LHD;
            for (int idx = t; idx < 32 * 16; idx += NTHR) {
                int r = idx >> 4, c4 = (idx & 15) * 4;
                int lg = lBase + r;
                float4 v = make_float4(0.f, 0.f, 0.f, 0.f);
                if (lg < Lq) v = *(const float4*)(qp + lg * HD + c4);
                float* d = Qs + r * SK + c4;
                d[0] = v.x; d[1] = v.y; d[2] = v.z; d[3] = v.w;
            }
        }
        __syncthreads();

        int moff[9];
#pragma unroll
        for (int j = 0; j < 9; j++) {
            int m = j * 32 + lane;
            moff[j] = (m < Lq ? m : Lq - 1) * SK;
        }

        float acc[2][9];
#pragma unroll
        for (int i = 0; i < 2; i++)
#pragma unroll
            for (int j = 0; j < 9; j++) acc[i][j] = 0.0f;

        const float* qbase = Qs + wid * 2 * SK;
#pragma unroll 4
        for (int hd = 0; hd < HD; hd++) {
            float q0 = qbase[hd];
            float q1 = qbase[SK + hd];
            float kk[9];
#pragma unroll
            for (int j = 0; j < 9; j++) kk[j] = Ks[moff[j] + hd];
#pragma unroll
            for (int j = 0; j < 9; j++) {
                acc[0][j] = fmaf(q0, kk[j], acc[0][j]);
                acc[1][j] = fmaf(q1, kk[j], acc[1][j]);
            }
        }

#pragma unroll
        for (int i = 0; i < 2; i++) {
            int row = lBase + wid * 2 + i;
            float mx = -INFINITY;
#pragma unroll
            for (int j = 0; j < 9; j++) {
                bool valid = (j * 32 + lane) < Lq;
                acc[i][j] = valid ? acc[i][j] * 0.125f : -INFINITY;
                mx = fmaxf(mx, acc[i][j]);
            }
#pragma unroll
            for (int off = 16; off > 0; off >>= 1)
                mx = fmaxf(mx, __shfl_xor_sync(0xffffffffu, mx, off));
            float s = 0.0f;
#pragma unroll
            for (int j = 0; j < 9; j++) {
                acc[i][j] = expf(acc[i][j] - mx);
                s += acc[i][j];
            }
#pragma unroll
            for (int off = 16; off > 0; off >>= 1)
                s += __shfl_xor_sync(0xffffffffu, s, off);
            float inv = 1.0f / s;
            if (row < Lq) {
                float* wr = w + ((size_t)nh * Lq + row) * Lq;
#pragma unroll
                for (int j = 0; j < 9; j++) {
                    int m = j * 32 + lane;
                    if (m < Lq) wr[m] = acc[i][j] * inv;
                }
            }
        }
        __syncthreads();
    }
}

// ---------------- phase: attn = weights @ V ----------------------------------
#define SV 68
#define SW 260
__device__ void attnv_phase(const float* __restrict__ w,
                            const float* __restrict__ Vh,
                            float* __restrict__ out,
                            float* smem) {
    float* Vs = smem;
    float* Ws = smem + Lq * SV;
    const int t = threadIdx.x;

    for (int u = blockIdx.x; u < 9 * NH; u += NBLK) {
        const int nh = u / 9;
        const int lBase = (u - nh * 9) * 32;
        const int n = nh / Hh, h = nh - n * Hh;

        {
            const float* vp = Vh + (size_t)nh * LHD;
            for (int idx = t; idx < Lq * 16; idx += NTHR) {
                int r = idx >> 4, c4 = (idx & 15) * 4;
                float4 v = *(const float4*)(vp + r * HD + c4);
                *(float4*)(Vs + r * SV + c4) = v;
            }
            for (int idx = t; idx < 32 * Lq; idx += NTHR) {
                int r = idx / Lq, c = idx - r * Lq;
                int lg = lBase + r;
                Ws[r * SW + c] = (lg < Lq)
                    ? w[((size_t)nh * Lq + lg) * Lq + c] : 0.0f;
            }
        }
        __syncthreads();

        const int l = t >> 4;             // 0..31
        const int hb = (t & 15) * 4;      // 4-col strip
        const float* wrow = Ws + l * SW;

        float a0 = 0, a1 = 0, a2 = 0, a3 = 0;
#pragma unroll 4
        for (int m = 0; m < Lq; m++) {
            float wv = wrow[m];
            float4 v = *(const float4*)(Vs + m * SV + hb);
            a0 = fmaf(wv, v.x, a0); a1 = fmaf(wv, v.y, a1);
            a2 = fmaf(wv, v.z, a2); a3 = fmaf(wv, v.w, a3);
        }

        int lg = lBase + l;
        if (lg < Lq) {
            float* p = out + ((size_t)lg * Nb + n) * Dm + h * HD + hb;
            p[0] = a0; p[1] = a1; p[2] = a2; p[3] = a3;
        }
        __syncthreads();
    }
}

// ---------------- the single fused kernel ------------------------------------
#define DSMEM_BYTES ((Lq * SV + 32 * SW) * 4)   // 103,184 B

__global__ void __launch_bounds__(NTHR, 1)
fused_block(const float* __restrict__ x,
            const float* __restrict__ in_proj_w,
            const float* __restrict__ in_proj_b,
            const float* __restrict__ out_proj_w,
            const float* __restrict__ out_proj_b,
            const float* __restrict__ ln1_g, const float* __restrict__ ln1_b,
            const float* __restrict__ ln2_g, const float* __restrict__ ln2_b,
            const float* __restrict__ fc_w,  const float* __restrict__ fc_b,
            float* __restrict__ out_x, float* __restrict__ out_w) {
    extern __shared__ float dsm[];

    // 1) LN1: x -> g_h
    ln_phase(x, ln1_g, ln1_b, g_h);
    grid_bar(0);

    // 2) qkv = g_h @ in_proj_w^T + b  -> head-major g_qkv
    gemm_phase(g_h, in_proj_w, in_proj_b, nullptr, g_qkv,
               D3 / 128, (D3 / 128) * 129, 4, dsm);
    grid_bar(1);

    // 3) fused scores + softmax -> out_w (final weights)
    scores_phase(g_qkv, g_qkv + X_ELEMS, out_w, dsm);
    grid_bar(2);

    // 4) attn = weights @ V -> g_attn
    attnv_phase(out_w, g_qkv + 2 * X_ELEMS, g_attn, dsm);
    grid_bar(3);

    // 5) x1 = x + attn @ out_proj_w^T + b
    gemm_phase(g_attn, out_proj_w, out_proj_b, x, g_x1,
               Dm / 128, (Dm / 128) * 129, 2, dsm);
    grid_bar(4);

    // 6) LN2: x1 -> g_h
    ln_phase(g_x1, ln2_g, ln2_b, g_h);
    grid_bar(5);

    // 7) out_x = x1 + quickGELU(g_h @ fc_w^T + fc_b)
    gemm_phase(g_h, fc_w, fc_b, g_x1, out_x,
               Dm / 128, (Dm / 128) * 129, 3, dsm);
}

// ---------------------------------------------------------------------------
extern "C" void kernel_launch(void* const* d_in, const int* in_sizes, int n_in,
                              void* d_out, int out_size) {
    const float* x          = (const float*)d_in[0];
    const float* in_proj_w  = (const float*)d_in[1];
    const float* in_proj_b  = (const float*)d_in[2];
    const float* out_proj_w = (const float*)d_in[3];
    const float* out_proj_b = (const float*)d_in[4];
    const float* ln1_g      = (const float*)d_in[5];
    const float* ln1_b      = (const float*)d_in[6];
    const float* ln2_g      = (const float*)d_in[7];
    const float* ln2_b      = (const float*)d_in[8];
    const float* fc_w       = (const float*)d_in[9];
    const float* fc_b       = (const float*)d_in[10];

    float* out_x = (float*)d_out;
    float* out_w = (float*)d_out + X_ELEMS;

    static int configured = 0;
    if (!configured) {
        cudaFuncSetAttribute(fused_block,
                             cudaFuncAttributeMaxDynamicSharedMemorySize,
                             DSMEM_BYTES);
        configured = 1;
    }

    fused_block<<<NBLK, NTHR, DSMEM_BYTES>>>(
        x, in_proj_w, in_proj_b, out_proj_w, out_proj_b,
        ln1_g, ln1_b, ln2_g, ln2_b, fc_w, fc_b, out_x, out_w);
}

// round 15
// speedup vs baseline: 12.8667x; 1.0807x over previous
#include <cuda_runtime.h>
#include <math.h>
#include <stdint.h>

#define Lq 257
#define Nb 64
#define Dm 768
#define Hh 12
#define HD 64
#define NH (Nb * Hh)               // 768
#define Mrows (Lq * Nb)            // 16448
#define D3 (3 * Dm)                // 2304
#define LHD (Lq * HD)
#define X_ELEMS ((size_t)Mrows * Dm)

#define NBLK 148                   // persistent grid: 1 CTA/SM
#define NTHR 512                   // 16 warps
#define NUM_BAR 6

// ---------------- scratch (device globals; no allocation allowed) ----------
__device__ float g_h[Mrows * Dm];
__device__ float g_qkv[(size_t)Mrows * D3];   // head-major [which][nh][l][hd]
__device__ float g_attn[Mrows * Dm];
__device__ float g_x1[Mrows * Dm];
__device__ float g_win[(size_t)D3 * Dm];      // tf32-rounded weights
__device__ float g_wout[(size_t)Dm * Dm];
__device__ float g_wfc[(size_t)Dm * Dm];
__device__ unsigned g_bar[NUM_BAR];

// ---------------- PTX helpers ----------------------------------------------
__device__ __forceinline__ uint32_t f2tf(float f) {
    uint32_t r;
    asm("cvt.rna.tf32.f32 %0, %1;" : "=r"(r) : "f"(f));
    return r;
}
__device__ __forceinline__ float round_tf32(float f) { return __uint_as_float(f2tf(f)); }
__device__ __forceinline__ void mma_tf32(float* c, const uint32_t* a, const uint32_t* b) {
    asm volatile(
        "mma.sync.aligned.m16n8k8.row.col.f32.tf32.tf32.f32 "
        "{%0,%1,%2,%3}, {%4,%5,%6,%7}, {%8,%9}, {%0,%1,%2,%3};\n"
        : "+f"(c[0]), "+f"(c[1]), "+f"(c[2]), "+f"(c[3])
        : "r"(a[0]), "r"(a[1]), "r"(a[2]), "r"(a[3]), "r"(b[0]), "r"(b[1]));
}
__device__ __forceinline__ void cp_async16(void* smem, const void* gmem) {
    uint32_t s = (uint32_t)__cvta_generic_to_shared(smem);
    asm volatile("cp.async.ca.shared.global [%0], [%1], 16;\n" :: "r"(s), "l"(gmem));
}
__device__ __forceinline__ void cp_commit() { asm volatile("cp.async.commit_group;\n"); }
__device__ __forceinline__ void cp_wait0()  { asm volatile("cp.async.wait_group 0;\n"); }

// ---------------- software grid barrier (replay-safe ring) ------------------
__device__ __forceinline__ void grid_bar(int k) {
    __threadfence();
    __syncthreads();
    if (threadIdx.x == 0) {
        unsigned prev = atomicAdd(&g_bar[k], 1u);
        if (prev == NBLK - 1) {
            int km1 = (k + NUM_BAR - 1) % NUM_BAR;
            atomicExch(&g_bar[km1], 0u);
        }
        unsigned v;
        do {
            asm volatile("ld.acquire.gpu.u32 %0, [%1];" : "=r"(v) : "l"(&g_bar[k]) : "memory");
        } while (v < NBLK);
    }
    __syncthreads();
}

// ---------------- phase: round weights to tf32 ------------------------------
__device__ void round_phase(const float* __restrict__ in, float* __restrict__ out, int n4) {
    int stride = NBLK * NTHR;
    for (int i = blockIdx.x * NTHR + threadIdx.x; i < n4; i += stride) {
        float4 v = ((const float4*)in)[i];
        v.x = round_tf32(v.x); v.y = round_tf32(v.y);
        v.z = round_tf32(v.z); v.w = round_tf32(v.w);
        ((float4*)out)[i] = v;
    }
}

// ---------------- phase: LayerNorm, warp-per-row (tf32-rounded out) ---------
__device__ void ln_phase(const float* __restrict__ x,
                         const float* __restrict__ g,
                         const float* __restrict__ b,
                         float* __restrict__ out) {
    const int t = threadIdx.x;
    const int wid = t >> 5, lane = t & 31;
    for (int row = blockIdx.x * 16 + wid; row < Mrows; row += NBLK * 16) {
        const float* xr = x + (size_t)row * Dm;
        float v[24];
        float s = 0.0f;
#pragma unroll
        for (int k = 0; k < 24; k++) { v[k] = xr[lane + k * 32]; s += v[k]; }
#pragma unroll
        for (int off = 16; off > 0; off >>= 1)
            s += __shfl_xor_sync(0xffffffffu, s, off);
        float mu = s * (1.0f / Dm);

        float sq = 0.0f;
#pragma unroll
        for (int k = 0; k < 24; k++) { float d = v[k] - mu; sq += d * d; }
#pragma unroll
        for (int off = 16; off > 0; off >>= 1)
            sq += __shfl_xor_sync(0xffffffffu, sq, off);
        float rstd = rsqrtf(sq * (1.0f / Dm) + 1e-5f);

        float* orow = out + (size_t)row * Dm;
#pragma unroll
        for (int k = 0; k < 24; k++) {
            int idx = lane + k * 32;
            orow[idx] = round_tf32((v[k] - mu) * rstd * g[idx] + b[idx]);
        }
    }
}

// ---------------- phase: TF32 MMA GEMM NT, K=768 -----------------------------
// A,B pre-rounded tf32. BM=BN=128, BK=16, 16 warps 4x4, warp tile 32x32.
// One __syncthreads per k-tile.
// epi: 2 = +bias+res, 3 = res + quickGELU(C+bias), 4 = +bias, head-major scatter
#define SROW 20
#define CPAD 132
__device__ void gemm_phase(const float* __restrict__ A,
                           const float* __restrict__ B,
                           const float* __restrict__ bias,
                           const float* __restrict__ res,
                           float* __restrict__ C,
                           int nTilesX, int nTiles, int epi,
                           float* smem) {
    float* Ab[2] = { smem,        smem + 2560 };
    float* Bb[2] = { smem + 5120, smem + 7680 };
    float* Cs = smem;

    const int t = threadIdx.x;
    const int wid = t >> 5, lane = t & 31;
    const int wm = wid >> 2, wn = wid & 3;        // 4 x 4 warp grid
    const int g = lane >> 2, tq = lane & 3;
    const int lr = t >> 2, lc = (t & 3) * 4;      // 128 rows x 16 cols loaders
    const int Nc = nTilesX * 128;

    for (int tile = blockIdx.x; tile < nTiles; tile += NBLK) {
        const int bx = tile % nTilesX, by = tile / nTilesX;
        const int mBase = by * 128, nBase = bx * 128;

        float acc[2][4][4];
#pragma unroll
        for (int i = 0; i < 2; i++)
#pragma unroll
            for (int j = 0; j < 4; j++)
#pragma unroll
                for (int q = 0; q < 4; q++) acc[i][j][q] = 0.0f;

        int arow = mBase + lr; if (arow >= Mrows) arow = Mrows - 1;
        const float* ap = A + (size_t)arow * Dm + lc;
        const float* bp = B + (size_t)(nBase + lr) * Dm + lc;

#define LOAD_TILE(stage, k0)                                              \
        do {                                                              \
            cp_async16(&Ab[stage][lr * SROW + lc], ap + (k0));            \
            cp_async16(&Bb[stage][lr * SROW + lc], bp + (k0));            \
        } while (0)

        LOAD_TILE(0, 0);
        cp_commit();

        const int T = Dm / 16;   // 48
        for (int kt = 0; kt < T; kt++) {
            cp_wait0();
            __syncthreads();          // data for kt ready; stage (kt+1)&1 free
            if (kt + 1 < T) {
                LOAD_TILE((kt + 1) & 1, (kt + 1) * 16);
                cp_commit();
            }

            const float* as = Ab[kt & 1];
            const float* bs = Bb[kt & 1];
#pragma unroll
            for (int ks = 0; ks < 2; ks++) {
                const int kk = ks * 8 + tq;
                uint32_t af[2][4];
#pragma unroll
                for (int mt = 0; mt < 2; mt++) {
                    int m0 = wm * 32 + mt * 16;
                    af[mt][0] = __float_as_uint(as[(m0 + g)     * SROW + kk]);
                    af[mt][1] = __float_as_uint(as[(m0 + g + 8) * SROW + kk]);
                    af[mt][2] = __float_as_uint(as[(m0 + g)     * SROW + kk + 4]);
                    af[mt][3] = __float_as_uint(as[(m0 + g + 8) * SROW + kk + 4]);
                }
                uint32_t bf[4][2];
#pragma unroll
                for (int nt = 0; nt < 4; nt++) {
                    int n0 = wn * 32 + nt * 8;
                    bf[nt][0] = __float_as_uint(bs[(n0 + g) * SROW + kk]);
                    bf[nt][1] = __float_as_uint(bs[(n0 + g) * SROW + kk + 4]);
                }
#pragma unroll
                for (int mt = 0; mt < 2; mt++)
#pragma unroll
                    for (int nt = 0; nt < 4; nt++)
                        mma_tf32(acc[mt][nt], af[mt], bf[nt]);
            }
        }
#undef LOAD_TILE
        __syncthreads();   // all warps done computing before Cs overwrites Ab/Bb

        // stage accumulators (+bias) into Cs[128][CPAD]
#pragma unroll
        for (int mt = 0; mt < 2; mt++) {
#pragma unroll
            for (int nt = 0; nt < 4; nt++) {
                int cl = wn * 32 + nt * 8 + 2 * tq;
                float bv0 = bias[nBase + cl], bv1 = bias[nBase + cl + 1];
#pragma unroll
                for (int half = 0; half < 2; half++) {
                    int rl = wm * 32 + mt * 16 + g + half * 8;
                    Cs[rl * CPAD + cl]     = acc[mt][nt][half * 2]     + bv0;
                    Cs[rl * CPAD + cl + 1] = acc[mt][nt][half * 2 + 1] + bv1;
                }
            }
        }
        __syncthreads();

        if (epi == 4) {
            // head-major scatter: each thread 32 contiguous floats (128 B)
            int rloc = t & 127;
            int q    = t >> 7;
            int row = mBase + rloc;
            if (row < Mrows) {
                int l = row >> 6, n = row & 63;
                int c0 = nBase + (q >> 1) * 64;
                int which = c0 / Dm;
                int h = (c0 - which * Dm) >> 6;
                float* dst = C + ((size_t)which * X_ELEMS)
                           + ((size_t)(n * Hh + h) * Lq + l) * HD + (q & 1) * 32;
                const float* src = Cs + rloc * CPAD + (q >> 1) * 64 + (q & 1) * 32;
#pragma unroll
                for (int k4 = 0; k4 < 8; k4++)
                    ((float4*)dst)[k4] = *(const float4*)(src + k4 * 4);
            }
        } else {
            for (int idx = t; idx < 128 * 32; idx += NTHR) {
                int r = idx >> 5, c4 = (idx & 31) << 2;
                int row = mBase + r;
                if (row >= Mrows) continue;
                float4 v = *(const float4*)(Cs + r * CPAD + c4);
                size_t off = (size_t)row * Nc + nBase + c4;
                float4 rr = *(const float4*)(res + off);
                if (epi == 2) {
                    v.x += rr.x; v.y += rr.y; v.z += rr.z; v.w += rr.w;
                } else {
                    v.x = rr.x + v.x / (1.0f + expf(-1.702f * v.x));
                    v.y = rr.y + v.y / (1.0f + expf(-1.702f * v.y));
                    v.z = rr.z + v.z / (1.0f + expf(-1.702f * v.z));
                    v.w = rr.w + v.w / (1.0f + expf(-1.702f * v.w));
                }
                *(float4*)(C + off) = v;
            }
        }
        __syncthreads();
    }
}

// ---------------- phase: fused scores + softmax ------------------------------
#define SK 65
__device__ void scores_phase(const float* __restrict__ Qh,
                             const float* __restrict__ Kh,
                             float* __restrict__ w,
                             float* smem) {
    float* Ks = smem;
    float* Qs = smem + Lq * SK;
    const int t = threadIdx.x;
    const int lane = t & 31, wid = t >> 5;

    for (int u = blockIdx.x; u < 9 * NH; u += NBLK) {
        const int nh = u / 9;
        const int lBase = (u - nh * 9) * 32;

        {
            const float* kp = Kh + (size_t)nh * LHD;
            for (int idx = t; idx < Lq * 16; idx += NTHR) {
                int r = idx >> 4, c4 = (idx & 15) * 4;
                float4 v = *(const float4*)(kp + r * HD + c4);
                float* d = Ks + r * SK + c4;
                d[0] = v.x; d[1] = v.y; d[2] = v.z; d[3] = v.w;
            }
            const float* qp = Qh + (size_t)nh * LHD;
            for (int idx = t; idx < 32 * 16; idx += NTHR) {
                int r = idx >> 4, c4 = (idx & 15) * 4;
                int lg = lBase + r;
                float4 v = make_float4(0.f, 0.f, 0.f, 0.f);
                if (lg < Lq) v = *(const float4*)(qp + lg * HD + c4);
                float* d = Qs + r * SK + c4;
                d[0] = v.x; d[1] = v.y; d[2] = v.z; d[3] = v.w;
            }
        }
        __syncthreads();

        int moff[9];
#pragma unroll
        for (int j = 0; j < 9; j++) {
            int m = j * 32 + lane;
            moff[j] = (m < Lq ? m : Lq - 1) * SK;
        }

        float acc[2][9];
#pragma unroll
        for (int i = 0; i < 2; i++)
#pragma unroll
            for (int j = 0; j < 9; j++) acc[i][j] = 0.0f;

        const float* qbase = Qs + wid * 2 * SK;
#pragma unroll 4
        for (int hd = 0; hd < HD; hd++) {
            float q0 = qbase[hd];
            float q1 = qbase[SK + hd];
            float kk[9];
#pragma unroll
            for (int j = 0; j < 9; j++) kk[j] = Ks[moff[j] + hd];
#pragma unroll
            for (int j = 0; j < 9; j++) {
                acc[0][j] = fmaf(q0, kk[j], acc[0][j]);
                acc[1][j] = fmaf(q1, kk[j], acc[1][j]);
            }
        }

#pragma unroll
        for (int i = 0; i < 2; i++) {
            int row = lBase + wid * 2 + i;
            float mx = -INFINITY;
#pragma unroll
            for (int j = 0; j < 9; j++) {
                bool valid = (j * 32 + lane) < Lq;
                acc[i][j] = valid ? acc[i][j] * 0.125f : -INFINITY;
                mx = fmaxf(mx, acc[i][j]);
            }
#pragma unroll
            for (int off = 16; off > 0; off >>= 1)
                mx = fmaxf(mx, __shfl_xor_sync(0xffffffffu, mx, off));
            float s = 0.0f;
#pragma unroll
            for (int j = 0; j < 9; j++) {
                acc[i][j] = expf(acc[i][j] - mx);
                s += acc[i][j];
            }
#pragma unroll
            for (int off = 16; off > 0; off >>= 1)
                s += __shfl_xor_sync(0xffffffffu, s, off);
            float inv = 1.0f / s;
            if (row < Lq) {
                float* wr = w + ((size_t)nh * Lq + row) * Lq;
#pragma unroll
                for (int j = 0; j < 9; j++) {
                    int m = j * 32 + lane;
                    if (m < Lq) wr[m] = acc[i][j] * inv;
                }
            }
        }
        __syncthreads();
    }
}

// ---------------- phase: attn = weights @ V (tf32-rounded out) ---------------
#define SV 68
#define SW 260
__device__ void attnv_phase(const float* __restrict__ w,
                            const float* __restrict__ Vh,
                            float* __restrict__ out,
                            float* smem) {
    float* Vs = smem;
    float* Ws = smem + Lq * SV;
    const int t = threadIdx.x;

    for (int u = blockIdx.x; u < 9 * NH; u += NBLK) {
        const int nh = u / 9;
        const int lBase = (u - nh * 9) * 32;
        const int n = nh / Hh, h = nh - n * Hh;

        {
            const float* vp = Vh + (size_t)nh * LHD;
            for (int idx = t; idx < Lq * 16; idx += NTHR) {
                int r = idx >> 4, c4 = (idx & 15) * 4;
                float4 v = *(const float4*)(vp + r * HD + c4);
                *(float4*)(Vs + r * SV + c4) = v;
            }
            for (int idx = t; idx < 32 * Lq; idx += NTHR) {
                int r = idx / Lq, c = idx - r * Lq;
                int lg = lBase + r;
                Ws[r * SW + c] = (lg < Lq)
                    ? w[((size_t)nh * Lq + lg) * Lq + c] : 0.0f;
            }
        }
        __syncthreads();

        const int l = t >> 4;
        const int hb = (t & 15) * 4;
        const float* wrow = Ws + l * SW;

        float a0 = 0, a1 = 0, a2 = 0, a3 = 0;
#pragma unroll 4
        for (int m = 0; m < Lq; m++) {
            float wv = wrow[m];
            float4 v = *(const float4*)(Vs + m * SV + hb);
            a0 = fmaf(wv, v.x, a0); a1 = fmaf(wv, v.y, a1);
            a2 = fmaf(wv, v.z, a2); a3 = fmaf(wv, v.w, a3);
        }

        int lg = lBase + l;
        if (lg < Lq) {
            float* p = out + ((size_t)lg * Nb + n) * Dm + h * HD + hb;
            p[0] = round_tf32(a0); p[1] = round_tf32(a1);
            p[2] = round_tf32(a2); p[3] = round_tf32(a3);
        }
        __syncthreads();
    }
}

// ---------------- the single fused kernel ------------------------------------
#define DSMEM_BYTES ((Lq * SV + 32 * SW) * 4)   // 103,184 B

__global__ void __launch_bounds__(NTHR, 1)
fused_block(const float* __restrict__ x,
            const float* __restrict__ in_proj_w,
            const float* __restrict__ in_proj_b,
            const float* __restrict__ out_proj_w,
            const float* __restrict__ out_proj_b,
            const float* __restrict__ ln1_g, const float* __restrict__ ln1_b,
            const float* __restrict__ ln2_g, const float* __restrict__ ln2_b,
            const float* __restrict__ fc_w,  const float* __restrict__ fc_b,
            float* __restrict__ out_x, float* __restrict__ out_w) {
    extern __shared__ float dsm[];

    // 1) LN1 + round weights (disjoint outputs, same phase)
    ln_phase(x, ln1_g, ln1_b, g_h);
    round_phase(in_proj_w,  g_win,  (D3 * Dm) / 4);
    round_phase(out_proj_w, g_wout, (Dm * Dm) / 4);
    round_phase(fc_w,       g_wfc,  (Dm * Dm) / 4);
    grid_bar(0);

    // 2) qkv = g_h @ win^T + b  -> head-major g_qkv
    gemm_phase(g_h, g_win, in_proj_b, nullptr, g_qkv,
               D3 / 128, (D3 / 128) * 129, 4, dsm);
    grid_bar(1);

    // 3) fused scores + softmax -> out_w (final weights)
    scores_phase(g_qkv, g_qkv + X_ELEMS, out_w, dsm);
    grid_bar(2);

    // 4) attn = weights @ V -> g_attn (rounded)
    attnv_phase(out_w, g_qkv + 2 * X_ELEMS, g_attn, dsm);
    grid_bar(3);

    // 5) x1 = x + attn @ wout^T + b
    gemm_phase(g_attn, g_wout, out_proj_b, x, g_x1,
               Dm / 128, (Dm / 128) * 129, 2, dsm);
    grid_bar(4);

    // 6) LN2: x1 -> g_h (rounded)
    ln_phase(g_x1, ln2_g, ln2_b, g_h);
    grid_bar(5);

    // 7) out_x = x1 + quickGELU(g_h @ wfc^T + fc_b)
    gemm_phase(g_h, g_wfc, fc_b, g_x1, out_x,
               Dm / 128, (Dm / 128) * 129, 3, dsm);
}

// ---------------------------------------------------------------------------
extern "C" void kernel_launch(void* const* d_in, const int* in_sizes, int n_in,
                              void* d_out, int out_size) {
    const float* x          = (const float*)d_in[0];
    const float* in_proj_w  = (const float*)d_in[1];
    const float* in_proj_b  = (const float*)d_in[2];
    const float* out_proj_w = (const float*)d_in[3];
    const float* out_proj_b = (const float*)d_in[4];
    const float* ln1_g      = (const float*)d_in[5];
    const float* ln1_b      = (const float*)d_in[6];
    const float* ln2_g      = (const float*)d_in[7];
    const float* ln2_b      = (const float*)d_in[8];
    const float* fc_w       = (const float*)d_in[9];
    const float* fc_b       = (const float*)d_in[10];

    float* out_x = (float*)d_out;
    float* out_w = (float*)d_out + X_ELEMS;

    static int configured = 0;
    if (!configured) {
        cudaFuncSetAttribute(fused_block,
                             cudaFuncAttributeMaxDynamicSharedMemorySize,
                             DSMEM_BYTES);
        configured = 1;
    }

    fused_block<<<NBLK, NTHR, DSMEM_BYTES>>>(
        x, in_proj_w, in_proj_b, out_proj_w, out_proj_b,
        ln1_g, ln1_b, ln2_g, ln2_b, fc_w, fc_b, out_x, out_w);
}

// round 16
// speedup vs baseline: 14.5587x; 1.1315x over previous
#include <cuda_runtime.h>
#include <math.h>
#include <stdint.h>

#define Lq 257
#define Nb 64
#define Dm 768
#define Hh 12
#define HD 64
#define NH (Nb * Hh)               // 768
#define Mrows (Lq * Nb)            // 16448
#define D3 (3 * Dm)                // 2304
#define LHD (Lq * HD)
#define X_ELEMS ((size_t)Mrows * Dm)

#define NBLK 148                   // persistent grid: 1 CTA/SM
#define NTHR 512                   // 16 warps
#define NUM_BAR 5

// ---------------- scratch (device globals; no allocation allowed) ----------
__device__ float g_h[Mrows * Dm];
__device__ float g_qkv[(size_t)Mrows * D3];   // head-major [which][nh][l][hd]
__device__ float g_attn[Mrows * Dm];
__device__ float g_x1[Mrows * Dm];
__device__ float g_win[(size_t)D3 * Dm];      // tf32-rounded weights
__device__ float g_wout[(size_t)Dm * Dm];
__device__ float g_wfc[(size_t)Dm * Dm];
__device__ unsigned g_bar[NUM_BAR];

// ---------------- PTX helpers ----------------------------------------------
__device__ __forceinline__ uint32_t f2tf(float f) {
    uint32_t r;
    asm("cvt.rna.tf32.f32 %0, %1;" : "=r"(r) : "f"(f));
    return r;
}
__device__ __forceinline__ float round_tf32(float f) { return __uint_as_float(f2tf(f)); }
__device__ __forceinline__ void mma_tf32(float* c, const uint32_t* a, const uint32_t* b) {
    asm volatile(
        "mma.sync.aligned.m16n8k8.row.col.f32.tf32.tf32.f32 "
        "{%0,%1,%2,%3}, {%4,%5,%6,%7}, {%8,%9}, {%0,%1,%2,%3};\n"
        : "+f"(c[0]), "+f"(c[1]), "+f"(c[2]), "+f"(c[3])
        : "r"(a[0]), "r"(a[1]), "r"(a[2]), "r"(a[3]), "r"(b[0]), "r"(b[1]));
}
__device__ __forceinline__ void cp_async16(void* smem, const void* gmem) {
    uint32_t s = (uint32_t)__cvta_generic_to_shared(smem);
    asm volatile("cp.async.ca.shared.global [%0], [%1], 16;\n" :: "r"(s), "l"(gmem));
}
__device__ __forceinline__ void cp_commit() { asm volatile("cp.async.commit_group;\n"); }
__device__ __forceinline__ void cp_wait0()  { asm volatile("cp.async.wait_group 0;\n"); }

// ---------------- software grid barrier (replay-safe ring) ------------------
__device__ __forceinline__ void grid_bar(int k) {
    __threadfence();
    __syncthreads();
    if (threadIdx.x == 0) {
        unsigned prev = atomicAdd(&g_bar[k], 1u);
        if (prev == NBLK - 1) {
            int km1 = (k + NUM_BAR - 1) % NUM_BAR;
            atomicExch(&g_bar[km1], 0u);
        }
        unsigned v;
        do {
            asm volatile("ld.acquire.gpu.u32 %0, [%1];" : "=r"(v) : "l"(&g_bar[k]) : "memory");
        } while (v < NBLK);
    }
    __syncthreads();
}

// ---------------- phase: round weights to tf32 ------------------------------
__device__ void round_phase(const float* __restrict__ in, float* __restrict__ out, int n4) {
    int stride = NBLK * NTHR;
    for (int i = blockIdx.x * NTHR + threadIdx.x; i < n4; i += stride) {
        float4 v = ((const float4*)in)[i];
        v.x = round_tf32(v.x); v.y = round_tf32(v.y);
        v.z = round_tf32(v.z); v.w = round_tf32(v.w);
        ((float4*)out)[i] = v;
    }
}

// ---------------- phase: LayerNorm, warp-per-row (tf32-rounded out) ---------
__device__ void ln_phase(const float* __restrict__ x,
                         const float* __restrict__ g,
                         const float* __restrict__ b,
                         float* __restrict__ out) {
    const int t = threadIdx.x;
    const int wid = t >> 5, lane = t & 31;
    for (int row = blockIdx.x * 16 + wid; row < Mrows; row += NBLK * 16) {
        const float* xr = x + (size_t)row * Dm;
        float v[24];
        float s = 0.0f;
#pragma unroll
        for (int k = 0; k < 24; k++) { v[k] = xr[lane + k * 32]; s += v[k]; }
#pragma unroll
        for (int off = 16; off > 0; off >>= 1)
            s += __shfl_xor_sync(0xffffffffu, s, off);
        float mu = s * (1.0f / Dm);

        float sq = 0.0f;
#pragma unroll
        for (int k = 0; k < 24; k++) { float d = v[k] - mu; sq += d * d; }
#pragma unroll
        for (int off = 16; off > 0; off >>= 1)
            sq += __shfl_xor_sync(0xffffffffu, sq, off);
        float rstd = rsqrtf(sq * (1.0f / Dm) + 1e-5f);

        float* orow = out + (size_t)row * Dm;
#pragma unroll
        for (int k = 0; k < 24; k++) {
            int idx = lane + k * 32;
            orow[idx] = round_tf32((v[k] - mu) * rstd * g[idx] + b[idx]);
        }
    }
}

// ---------------- phase: TF32 MMA GEMM NT, K=768 -----------------------------
#define SROW 20
#define CPAD 132
__device__ void gemm_phase(const float* __restrict__ A,
                           const float* __restrict__ B,
                           const float* __restrict__ bias,
                           const float* __restrict__ res,
                           float* __restrict__ C,
                           int nTilesX, int nTiles, int epi,
                           float* smem) {
    float* Ab[2] = { smem,        smem + 2560 };
    float* Bb[2] = { smem + 5120, smem + 7680 };
    float* Cs = smem;

    const int t = threadIdx.x;
    const int wid = t >> 5, lane = t & 31;
    const int wm = wid >> 2, wn = wid & 3;        // 4 x 4 warp grid
    const int g = lane >> 2, tq = lane & 3;
    const int lr = t >> 2, lc = (t & 3) * 4;
    const int Nc = nTilesX * 128;

    for (int tile = blockIdx.x; tile < nTiles; tile += NBLK) {
        const int bx = tile % nTilesX, by = tile / nTilesX;
        const int mBase = by * 128, nBase = bx * 128;

        float acc[2][4][4];
#pragma unroll
        for (int i = 0; i < 2; i++)
#pragma unroll
            for (int j = 0; j < 4; j++)
#pragma unroll
                for (int q = 0; q < 4; q++) acc[i][j][q] = 0.0f;

        int arow = mBase + lr; if (arow >= Mrows) arow = Mrows - 1;
        const float* ap = A + (size_t)arow * Dm + lc;
        const float* bp = B + (size_t)(nBase + lr) * Dm + lc;

#define LOAD_TILE(stage, k0)                                              \
        do {                                                              \
            cp_async16(&Ab[stage][lr * SROW + lc], ap + (k0));            \
            cp_async16(&Bb[stage][lr * SROW + lc], bp + (k0));            \
        } while (0)

        LOAD_TILE(0, 0);
        cp_commit();

        const int T = Dm / 16;   // 48
        for (int kt = 0; kt < T; kt++) {
            cp_wait0();
            __syncthreads();
            if (kt + 1 < T) {
                LOAD_TILE((kt + 1) & 1, (kt + 1) * 16);
                cp_commit();
            }

            const float* as = Ab[kt & 1];
            const float* bs = Bb[kt & 1];
#pragma unroll
            for (int ks = 0; ks < 2; ks++) {
                const int kk = ks * 8 + tq;
                uint32_t af[2][4];
#pragma unroll
                for (int mt = 0; mt < 2; mt++) {
                    int m0 = wm * 32 + mt * 16;
                    af[mt][0] = __float_as_uint(as[(m0 + g)     * SROW + kk]);
                    af[mt][1] = __float_as_uint(as[(m0 + g + 8) * SROW + kk]);
                    af[mt][2] = __float_as_uint(as[(m0 + g)     * SROW + kk + 4]);
                    af[mt][3] = __float_as_uint(as[(m0 + g + 8) * SROW + kk + 4]);
                }
                uint32_t bf[4][2];
#pragma unroll
                for (int nt = 0; nt < 4; nt++) {
                    int n0 = wn * 32 + nt * 8;
                    bf[nt][0] = __float_as_uint(bs[(n0 + g) * SROW + kk]);
                    bf[nt][1] = __float_as_uint(bs[(n0 + g) * SROW + kk + 4]);
                }
#pragma unroll
                for (int mt = 0; mt < 2; mt++)
#pragma unroll
                    for (int nt = 0; nt < 4; nt++)
                        mma_tf32(acc[mt][nt], af[mt], bf[nt]);
            }
        }
#undef LOAD_TILE
        __syncthreads();

#pragma unroll
        for (int mt = 0; mt < 2; mt++) {
#pragma unroll
            for (int nt = 0; nt < 4; nt++) {
                int cl = wn * 32 + nt * 8 + 2 * tq;
                float bv0 = bias[nBase + cl], bv1 = bias[nBase + cl + 1];
#pragma unroll
                for (int half = 0; half < 2; half++) {
                    int rl = wm * 32 + mt * 16 + g + half * 8;
                    Cs[rl * CPAD + cl]     = acc[mt][nt][half * 2]     + bv0;
                    Cs[rl * CPAD + cl + 1] = acc[mt][nt][half * 2 + 1] + bv1;
                }
            }
        }
        __syncthreads();

        if (epi == 4) {
            int rloc = t & 127;
            int q    = t >> 7;
            int row = mBase + rloc;
            if (row < Mrows) {
                int l = row >> 6, n = row & 63;
                int c0 = nBase + (q >> 1) * 64;
                int which = c0 / Dm;
                int h = (c0 - which * Dm) >> 6;
                float* dst = C + ((size_t)which * X_ELEMS)
                           + ((size_t)(n * Hh + h) * Lq + l) * HD + (q & 1) * 32;
                const float* src = Cs + rloc * CPAD + (q >> 1) * 64 + (q & 1) * 32;
#pragma unroll
                for (int k4 = 0; k4 < 8; k4++)
                    ((float4*)dst)[k4] = *(const float4*)(src + k4 * 4);
            }
        } else {
            for (int idx = t; idx < 128 * 32; idx += NTHR) {
                int r = idx >> 5, c4 = (idx & 31) << 2;
                int row = mBase + r;
                if (row >= Mrows) continue;
                float4 v = *(const float4*)(Cs + r * CPAD + c4);
                size_t off = (size_t)row * Nc + nBase + c4;
                float4 rr = *(const float4*)(res + off);
                if (epi == 2) {
                    v.x += rr.x; v.y += rr.y; v.z += rr.z; v.w += rr.w;
                } else {
                    v.x = rr.x + v.x / (1.0f + expf(-1.702f * v.x));
                    v.y = rr.y + v.y / (1.0f + expf(-1.702f * v.y));
                    v.z = rr.z + v.z / (1.0f + expf(-1.702f * v.z));
                    v.w = rr.w + v.w / (1.0f + expf(-1.702f * v.w));
                }
                *(float4*)(C + off) = v;
            }
        }
        __syncthreads();
    }
}

// ---------------- fused attention: scores + softmax + attnV ------------------
// smem: Ks[264][SKA], Vs[264][SKA] (tf32-rounded), Qs[32][SKA], Ws[32][WSK]
#define SKA 68
#define WSK 268
#define OFF_V (264 * SKA)                 // 17952
#define OFF_Q (2 * 264 * SKA)             // 35904
#define OFF_W (OFF_Q + 32 * SKA)          // 38080
#define ATTN_FLOATS (OFF_W + 32 * WSK)    // 46656
__device__ void attn_phase(const float* __restrict__ Qh,
                           const float* __restrict__ Kh,
                           const float* __restrict__ Vh,
                           float* __restrict__ w,
                           float* __restrict__ attnOut,
                           float* sm) {
    float* Ks = sm;
    float* Vs = sm + OFF_V;
    float* Qs = sm + OFF_Q;
    float* Ws = sm + OFF_W;
    const int t = threadIdx.x;
    const int lane = t & 31, wid = t >> 5;
    const int g = lane >> 2, tq = lane & 3;

    for (int u = blockIdx.x; u < 9 * NH; u += NBLK) {
        const int nh = u / 9;
        const int lBase = (u - nh * 9) * 32;
        const int n = nh / Hh, h = nh - n * Hh;

        // ---- stage K, V (full head) and Q (32 rows, clamped) via cp.async --
        {
            const float* kp = Kh + (size_t)nh * LHD;
            const float* vp = Vh + (size_t)nh * LHD;
            for (int idx = t; idx < Lq * 16; idx += NTHR) {
                int r = idx >> 4, c4 = (idx & 15) * 4;
                cp_async16(&Ks[r * SKA + c4], kp + r * HD + c4);
                cp_async16(&Vs[r * SKA + c4], vp + r * HD + c4);
            }
            const float* qp = Qh + (size_t)nh * LHD;
            int r = t >> 4, c4 = (t & 15) * 4;
            int lg = lBase + r; if (lg >= Lq) lg = Lq - 1;
            cp_async16(&Qs[r * SKA + c4], qp + lg * HD + c4);
            // zero V pad rows 257..263 (mma K-padding)
            if (t < 112) {
                int pr = 257 + t / 16, pc = (t % 16) * 4;
                *(float4*)(Vs + pr * SKA + pc) = make_float4(0.f, 0.f, 0.f, 0.f);
            }
        }
        cp_commit();
        cp_wait0();
        __syncthreads();

        // ---- round V in place to tf32 (mma input) --------------------------
        for (int idx = t; idx < Lq * 16; idx += NTHR) {
            int r = idx >> 4, c4 = (idx & 15) * 4;
            float4 v = *(const float4*)(Vs + r * SKA + c4);
            v.x = round_tf32(v.x); v.y = round_tf32(v.y);
            v.z = round_tf32(v.z); v.w = round_tf32(v.w);
            *(float4*)(Vs + r * SKA + c4) = v;
        }

        // ---- scores (fp32, bit-identical order to R15) ---------------------
        int moff[9];
#pragma unroll
        for (int j = 0; j < 9; j++) {
            int m = j * 32 + lane;
            moff[j] = (m < Lq ? m : Lq - 1) * SKA;
        }

        float acc[2][9];
#pragma unroll
        for (int i = 0; i < 2; i++)
#pragma unroll
            for (int j = 0; j < 9; j++) acc[i][j] = 0.0f;

        const float4* qb0 = (const float4*)(Qs + (wid * 2) * SKA);
        const float4* qb1 = (const float4*)(Qs + (wid * 2 + 1) * SKA);
#pragma unroll 4
        for (int p = 0; p < 16; p++) {
            float4 q0 = qb0[p];
            float4 q1 = qb1[p];
#pragma unroll
            for (int j = 0; j < 9; j++) {
                float4 k4 = *(const float4*)(Ks + moff[j] + p * 4);
                acc[0][j] = fmaf(q0.x, k4.x, acc[0][j]);
                acc[0][j] = fmaf(q0.y, k4.y, acc[0][j]);
                acc[0][j] = fmaf(q0.z, k4.z, acc[0][j]);
                acc[0][j] = fmaf(q0.w, k4.w, acc[0][j]);
                acc[1][j] = fmaf(q1.x, k4.x, acc[1][j]);
                acc[1][j] = fmaf(q1.y, k4.y, acc[1][j]);
                acc[1][j] = fmaf(q1.z, k4.z, acc[1][j]);
                acc[1][j] = fmaf(q1.w, k4.w, acc[1][j]);
            }
        }

        // ---- softmax + store weights (gmem output + tf32 copy in smem) -----
#pragma unroll
        for (int i = 0; i < 2; i++) {
            int row = lBase + wid * 2 + i;
            float mx = -INFINITY;
#pragma unroll
            for (int j = 0; j < 9; j++) {
                bool valid = (j * 32 + lane) < Lq;
                acc[i][j] = valid ? acc[i][j] * 0.125f : -INFINITY;
                mx = fmaxf(mx, acc[i][j]);
            }
#pragma unroll
            for (int off = 16; off > 0; off >>= 1)
                mx = fmaxf(mx, __shfl_xor_sync(0xffffffffu, mx, off));
            float s = 0.0f;
#pragma unroll
            for (int j = 0; j < 9; j++) {
                acc[i][j] = expf(acc[i][j] - mx);
                s += acc[i][j];
            }
#pragma unroll
            for (int off = 16; off > 0; off >>= 1)
                s += __shfl_xor_sync(0xffffffffu, s, off);
            float inv = 1.0f / s;

            float* wsr = Ws + (wid * 2 + i) * WSK;
            float* wr  = w + ((size_t)nh * Lq + row) * Lq;
#pragma unroll
            for (int j = 0; j < 9; j++) {
                int m = j * 32 + lane;
                float val = acc[i][j] * inv;        // 0 for invalid m
                if (m < WSK) wsr[m] = round_tf32(val);
                if (row < Lq && m < Lq) wr[m] = val;
            }
        }
        __syncthreads();   // Ws + rounded Vs ready

        // ---- attnV via tf32 MMA: attn[32 l][64 hd] = Ws @ Vs ---------------
        {
            const int m0 = (wid >> 3) * 16;   // 2 m-tiles
            const int n0 = (wid & 7) * 8;     // 8 n-tiles
            float c[4] = {0.f, 0.f, 0.f, 0.f};
#pragma unroll 8
            for (int ks = 0; ks < 33; ks++) {
                int kk = ks * 8 + tq;
                uint32_t a[4], b[2];
                a[0] = __float_as_uint(Ws[(m0 + g)     * WSK + kk]);
                a[1] = __float_as_uint(Ws[(m0 + g + 8) * WSK + kk]);
                a[2] = __float_as_uint(Ws[(m0 + g)     * WSK + kk + 4]);
                a[3] = __float_as_uint(Ws[(m0 + g + 8) * WSK + kk + 4]);
                b[0] = __float_as_uint(Vs[kk       * SKA + n0 + g]);
                b[1] = __float_as_uint(Vs[(kk + 4) * SKA + n0 + g]);
                mma_tf32(c, a, b);
            }
            int colBase = h * HD + n0 + 2 * tq;
            int l0 = lBase + m0 + g;
            if (l0 < Lq) {
                float* p = attnOut + ((size_t)l0 * Nb + n) * Dm + colBase;
                p[0] = round_tf32(c[0]); p[1] = round_tf32(c[1]);
            }
            int l1 = l0 + 8;
            if (l1 < Lq) {
                float* p = attnOut + ((size_t)l1 * Nb + n) * Dm + colBase;
                p[0] = round_tf32(c[2]); p[1] = round_tf32(c[3]);
            }
        }
        __syncthreads();   // before next unit overwrites smem
    }
}

// ---------------- the single fused kernel ------------------------------------
#define DSMEM_BYTES (ATTN_FLOATS * 4)   // 186,624 B

__global__ void __launch_bounds__(NTHR, 1)
fused_block(const float* __restrict__ x,
            const float* __restrict__ in_proj_w,
            const float* __restrict__ in_proj_b,
            const float* __restrict__ out_proj_w,
            const float* __restrict__ out_proj_b,
            const float* __restrict__ ln1_g, const float* __restrict__ ln1_b,
            const float* __restrict__ ln2_g, const float* __restrict__ ln2_b,
            const float* __restrict__ fc_w,  const float* __restrict__ fc_b,
            float* __restrict__ out_x, float* __restrict__ out_w) {
    extern __shared__ float dsm[];

    // 1) LN1 + round weights
    ln_phase(x, ln1_g, ln1_b, g_h);
    round_phase(in_proj_w,  g_win,  (D3 * Dm) / 4);
    round_phase(out_proj_w, g_wout, (Dm * Dm) / 4);
    round_phase(fc_w,       g_wfc,  (Dm * Dm) / 4);
    grid_bar(0);

    // 2) qkv = g_h @ win^T + b  -> head-major g_qkv
    gemm_phase(g_h, g_win, in_proj_b, nullptr, g_qkv,
               D3 / 128, (D3 / 128) * 129, 4, dsm);
    grid_bar(1);

    // 3) fused attention: scores + softmax -> out_w; attnV -> g_attn
    attn_phase(g_qkv, g_qkv + X_ELEMS, g_qkv + 2 * X_ELEMS,
               out_w, g_attn, dsm);
    grid_bar(2);

    // 4) x1 = x + attn @ wout^T + b
    gemm_phase(g_attn, g_wout, out_proj_b, x, g_x1,
               Dm / 128, (Dm / 128) * 129, 2, dsm);
    grid_bar(3);

    // 5) LN2: x1 -> g_h (rounded)
    ln_phase(g_x1, ln2_g, ln2_b, g_h);
    grid_bar(4);

    // 6) out_x = x1 + quickGELU(g_h @ wfc^T + fc_b)
    gemm_phase(g_h, g_wfc, fc_b, g_x1, out_x,
               Dm / 128, (Dm / 128) * 129, 3, dsm);
}

// ---------------------------------------------------------------------------
extern "C" void kernel_launch(void* const* d_in, const int* in_sizes, int n_in,
                              void* d_out, int out_size) {
    const float* x          = (const float*)d_in[0];
    const float* in_proj_w  = (const float*)d_in[1];
    const float* in_proj_b  = (const float*)d_in[2];
    const float* out_proj_w = (const float*)d_in[3];
    const float* out_proj_b = (const float*)d_in[4];
    const float* ln1_g      = (const float*)d_in[5];
    const float* ln1_b      = (const float*)d_in[6];
    const float* ln2_g      = (const float*)d_in[7];
    const float* ln2_b      = (const float*)d_in[8];
    const float* fc_w       = (const float*)d_in[9];
    const float* fc_b       = (const float*)d_in[10];

    float* out_x = (float*)d_out;
    float* out_w = (float*)d_out + X_ELEMS;

    static int configured = 0;
    if (!configured) {
        cudaFuncSetAttribute(fused_block,
                             cudaFuncAttributeMaxDynamicSharedMemorySize,
                             DSMEM_BYTES);
        configured = 1;
    }

    fused_block<<<NBLK, NTHR, DSMEM_BYTES>>>(
        x, in_proj_w, in_proj_b, out_proj_w, out_proj_b,
        ln1_g, ln1_b, ln2_g, ln2_b, fc_w, fc_b, out_x, out_w);
}

// round 17
// speedup vs baseline: 20.2633x; 1.3918x over previous
#include <cuda_runtime.h>
#include <math.h>
#include <stdint.h>

#define Lq 257
#define Nb 64
#define Dm 768
#define Hh 12
#define HD 64
#define NH (Nb * Hh)               // 768
#define Mrows (Lq * Nb)            // 16448
#define D3 (3 * Dm)                // 2304
#define LHD (Lq * HD)
#define X_ELEMS ((size_t)Mrows * Dm)

#define NBLK 148                   // persistent grid: 1 CTA/SM
#define NTHR 256                   // 8 warps (big per-warp tiles)
#define NUM_BAR 5

// ---------------- scratch (device globals; no allocation allowed) ----------
__device__ float g_h[Mrows * Dm];
__device__ float g_qkv[(size_t)Mrows * D3];   // head-major [which][nh][l][hd]
__device__ float g_attn[Mrows * Dm];
__device__ float g_x1[Mrows * Dm];
__device__ float g_win[(size_t)D3 * Dm];      // tf32-rounded weights
__device__ float g_wout[(size_t)Dm * Dm];
__device__ float g_wfc[(size_t)Dm * Dm];
__device__ unsigned g_bar[NUM_BAR];

// ---------------- PTX helpers ----------------------------------------------
__device__ __forceinline__ uint32_t f2tf(float f) {
    uint32_t r;
    asm("cvt.rna.tf32.f32 %0, %1;" : "=r"(r) : "f"(f));
    return r;
}
__device__ __forceinline__ float round_tf32(float f) { return __uint_as_float(f2tf(f)); }
__device__ __forceinline__ void mma_tf32(float* c, const uint32_t* a, const uint32_t* b) {
    asm volatile(
        "mma.sync.aligned.m16n8k8.row.col.f32.tf32.tf32.f32 "
        "{%0,%1,%2,%3}, {%4,%5,%6,%7}, {%8,%9}, {%0,%1,%2,%3};\n"
        : "+f"(c[0]), "+f"(c[1]), "+f"(c[2]), "+f"(c[3])
        : "r"(a[0]), "r"(a[1]), "r"(a[2]), "r"(a[3]), "r"(b[0]), "r"(b[1]));
}
__device__ __forceinline__ void cp_async16(void* smem, const void* gmem) {
    uint32_t s = (uint32_t)__cvta_generic_to_shared(smem);
    asm volatile("cp.async.ca.shared.global [%0], [%1], 16;\n" :: "r"(s), "l"(gmem));
}
__device__ __forceinline__ void cp_commit() { asm volatile("cp.async.commit_group;\n"); }
__device__ __forceinline__ void cp_wait0()  { asm volatile("cp.async.wait_group 0;\n"); }

// ---------------- software grid barrier (replay-safe ring) ------------------
__device__ __forceinline__ void grid_bar(int k) {
    __threadfence();
    __syncthreads();
    if (threadIdx.x == 0) {
        unsigned prev = atomicAdd(&g_bar[k], 1u);
        if (prev == NBLK - 1) {
            int km1 = (k + NUM_BAR - 1) % NUM_BAR;
            atomicExch(&g_bar[km1], 0u);
        }
        unsigned v;
        do {
            asm volatile("ld.acquire.gpu.u32 %0, [%1];" : "=r"(v) : "l"(&g_bar[k]) : "memory");
        } while (v < NBLK);
    }
    __syncthreads();
}

// ---------------- phase: round weights to tf32 ------------------------------
__device__ void round_phase(const float* __restrict__ in, float* __restrict__ out, int n4) {
    int stride = NBLK * NTHR;
    for (int i = blockIdx.x * NTHR + threadIdx.x; i < n4; i += stride) {
        float4 v = ((const float4*)in)[i];
        v.x = round_tf32(v.x); v.y = round_tf32(v.y);
        v.z = round_tf32(v.z); v.w = round_tf32(v.w);
        ((float4*)out)[i] = v;
    }
}

// ---------------- phase: LayerNorm, warp-per-row (tf32-rounded out) ---------
__device__ void ln_phase(const float* __restrict__ x,
                         const float* __restrict__ g,
                         const float* __restrict__ b,
                         float* __restrict__ out) {
    const int t = threadIdx.x;
    const int wid = t >> 5, lane = t & 31;
    for (int row = blockIdx.x * 8 + wid; row < Mrows; row += NBLK * 8) {
        const float* xr = x + (size_t)row * Dm;
        float v[24];
        float s = 0.0f;
#pragma unroll
        for (int k = 0; k < 24; k++) { v[k] = xr[lane + k * 32]; s += v[k]; }
#pragma unroll
        for (int off = 16; off > 0; off >>= 1)
            s += __shfl_xor_sync(0xffffffffu, s, off);
        float mu = s * (1.0f / Dm);

        float sq = 0.0f;
#pragma unroll
        for (int k = 0; k < 24; k++) { float d = v[k] - mu; sq += d * d; }
#pragma unroll
        for (int off = 16; off > 0; off >>= 1)
            sq += __shfl_xor_sync(0xffffffffu, sq, off);
        float rstd = rsqrtf(sq * (1.0f / Dm) + 1e-5f);

        float* orow = out + (size_t)row * Dm;
#pragma unroll
        for (int k = 0; k < 24; k++) {
            int idx = lane + k * 32;
            orow[idx] = round_tf32((v[k] - mu) * rstd * g[idx] + b[idx]);
        }
    }
}

// ---------------- phase: TF32 MMA GEMM NT, K=768 -----------------------------
// A,B pre-rounded tf32. BM=128, BN=256, BK=16. 8 warps in 2x4 grid,
// warp tile 64x64 (acc 128 regs). One __syncthreads per k-tile.
// epi: 2 = +bias+res, 3 = res + quickGELU(C+bias), 4 = +bias, head-major scatter
#define SROW 20
#define CPADE 264
__device__ void gemm_phase(const float* __restrict__ A,
                           const float* __restrict__ B,
                           const float* __restrict__ bias,
                           const float* __restrict__ res,
                           float* __restrict__ C,
                           int nTilesX, int nTiles, int epi,
                           float* smem) {
    float* Ab[2] = { smem,        smem + 2560 };
    float* Bb[2] = { smem + 5120, smem + 10240 };
    float* Cs = smem;

    const int t = threadIdx.x;
    const int wid = t >> 5, lane = t & 31;
    const int wm = wid >> 2, wn = wid & 3;        // 2 x 4 warp grid, 64x64 tiles
    const int g = lane >> 2, tq = lane & 3;
    const int lc = (t & 3) * 4;
    const int lrow = t >> 2;                      // 0..63
    const int Nc = nTilesX * 256;

    for (int tile = blockIdx.x; tile < nTiles; tile += NBLK) {
        const int bx = tile % nTilesX, by = tile / nTilesX;
        const int mBase = by * 128, nBase = bx * 256;

        float acc[4][8][4];
#pragma unroll
        for (int i = 0; i < 4; i++)
#pragma unroll
            for (int j = 0; j < 8; j++)
#pragma unroll
                for (int q = 0; q < 4; q++) acc[i][j][q] = 0.0f;

        int aR0 = mBase + lrow;      if (aR0 >= Mrows) aR0 = Mrows - 1;
        int aR1 = mBase + 64 + lrow; if (aR1 >= Mrows) aR1 = Mrows - 1;
        const float* ap0 = A + (size_t)aR0 * Dm + lc;
        const float* ap1 = A + (size_t)aR1 * Dm + lc;
        const float* bp0 = B + (size_t)(nBase + lrow) * Dm + lc;
        const float* bp1 = B + (size_t)(nBase + 64 + lrow) * Dm + lc;
        const float* bp2 = B + (size_t)(nBase + 128 + lrow) * Dm + lc;
        const float* bp3 = B + (size_t)(nBase + 192 + lrow) * Dm + lc;

#define LOAD_TILE(st, k0)                                                   \
        do {                                                                \
            cp_async16(&Ab[st][lrow * SROW + lc],         ap0 + (k0));      \
            cp_async16(&Ab[st][(lrow + 64) * SROW + lc],  ap1 + (k0));      \
            cp_async16(&Bb[st][lrow * SROW + lc],         bp0 + (k0));      \
            cp_async16(&Bb[st][(lrow + 64) * SROW + lc],  bp1 + (k0));      \
            cp_async16(&Bb[st][(lrow + 128) * SROW + lc], bp2 + (k0));      \
            cp_async16(&Bb[st][(lrow + 192) * SROW + lc], bp3 + (k0));      \
        } while (0)

        LOAD_TILE(0, 0);
        cp_commit();

        const int T = Dm / 16;   // 48
        for (int kt = 0; kt < T; kt++) {
            cp_wait0();
            __syncthreads();
            if (kt + 1 < T) {
                LOAD_TILE((kt + 1) & 1, (kt + 1) * 16);
                cp_commit();
            }

            const float* as = Ab[kt & 1];
            const float* bs = Bb[kt & 1];
#pragma unroll
            for (int ks = 0; ks < 2; ks++) {
                const int kk = ks * 8 + tq;
                uint32_t af[4][4];
#pragma unroll
                for (int mt = 0; mt < 4; mt++) {
                    int m0 = wm * 64 + mt * 16;
                    af[mt][0] = __float_as_uint(as[(m0 + g)     * SROW + kk]);
                    af[mt][1] = __float_as_uint(as[(m0 + g + 8) * SROW + kk]);
                    af[mt][2] = __float_as_uint(as[(m0 + g)     * SROW + kk + 4]);
                    af[mt][3] = __float_as_uint(as[(m0 + g + 8) * SROW + kk + 4]);
                }
                uint32_t bf[8][2];
#pragma unroll
                for (int nt = 0; nt < 8; nt++) {
                    int n0 = wn * 64 + nt * 8;
                    bf[nt][0] = __float_as_uint(bs[(n0 + g) * SROW + kk]);
                    bf[nt][1] = __float_as_uint(bs[(n0 + g) * SROW + kk + 4]);
                }
#pragma unroll
                for (int mt = 0; mt < 4; mt++)
#pragma unroll
                    for (int nt = 0; nt < 8; nt++)
                        mma_tf32(acc[mt][nt], af[mt], bf[nt]);
            }
        }
#undef LOAD_TILE
        __syncthreads();   // all warps done before Cs overwrites Ab/Bb

        // stage accumulators (+bias) into Cs[128][CPADE]
#pragma unroll
        for (int mt = 0; mt < 4; mt++) {
#pragma unroll
            for (int nt = 0; nt < 8; nt++) {
                int cl = wn * 64 + nt * 8 + 2 * tq;
                float bv0 = bias[nBase + cl], bv1 = bias[nBase + cl + 1];
#pragma unroll
                for (int half = 0; half < 2; half++) {
                    int rl = wm * 64 + mt * 16 + g + half * 8;
                    Cs[rl * CPADE + cl]     = acc[mt][nt][half * 2]     + bv0;
                    Cs[rl * CPADE + cl + 1] = acc[mt][nt][half * 2 + 1] + bv1;
                }
            }
        }
        __syncthreads();

        if (epi == 4) {
            // head-major scatter: thread handles 2 groups of 64 contiguous floats
            int rloc = t & 127;
            int gsel = t >> 7;            // 0..1
            int row = mBase + rloc;
            if (row < Mrows) {
                int l = row >> 6, n = row & 63;
#pragma unroll
                for (int gg = 0; gg < 2; gg++) {
                    int grp = gsel + gg * 2;
                    int c0 = nBase + grp * 64;
                    int which = c0 / Dm;
                    int h = (c0 - which * Dm) >> 6;
                    float* dst = C + (size_t)which * X_ELEMS
                               + ((size_t)(n * Hh + h) * Lq + l) * HD;
                    const float* src = Cs + rloc * CPADE + grp * 64;
#pragma unroll
                    for (int k4 = 0; k4 < 16; k4++)
                        ((float4*)dst)[k4] = *(const float4*)(src + k4 * 4);
                }
            }
        } else {
            for (int idx = t; idx < 128 * 64; idx += NTHR) {
                int r = idx >> 6, c4 = (idx & 63) << 2;
                int row = mBase + r;
                if (row >= Mrows) continue;
                float4 v = *(const float4*)(Cs + r * CPADE + c4);
                size_t off = (size_t)row * Nc + nBase + c4;
                float4 rr = *(const float4*)(res + off);
                if (epi == 2) {
                    v.x += rr.x; v.y += rr.y; v.z += rr.z; v.w += rr.w;
                } else {
                    v.x = rr.x + v.x / (1.0f + expf(-1.702f * v.x));
                    v.y = rr.y + v.y / (1.0f + expf(-1.702f * v.y));
                    v.z = rr.z + v.z / (1.0f + expf(-1.702f * v.z));
                    v.w = rr.w + v.w / (1.0f + expf(-1.702f * v.w));
                }
                *(float4*)(C + off) = v;
            }
        }
        __syncthreads();
    }
}

// ---------------- fused attention: scores + softmax + attnV ------------------
// 64-row l-chunks (5 per head). smem: Ks[264][SKA] (overlaid by Ws[64][WSK]
// after scores), Vs[264][SKA] (tf32-rounded in place), Qs[64][SKA].
#define SKA 68
#define WSK 268
#define OFF_V (264 * SKA)                 // 17952
#define OFF_Q (2 * 264 * SKA)             // 35904
#define ATTN_FLOATS (OFF_Q + 64 * SKA)    // 40256
__device__ void attn_phase(const float* __restrict__ Qh,
                           const float* __restrict__ Kh,
                           const float* __restrict__ Vh,
                           float* __restrict__ w,
                           float* __restrict__ attnOut,
                           float* sm) {
    float* Ks = sm;
    float* Vs = sm + OFF_V;
    float* Qs = sm + OFF_Q;
    float* Ws = sm;                       // overlays Ks after scores are done
    const int t = threadIdx.x;
    const int lane = t & 31, wid = t >> 5;
    const int g = lane >> 2, tq = lane & 3;

    for (int u = blockIdx.x; u < 5 * NH; u += NBLK) {
        const int nh = u / 5;
        const int lBase = (u - nh * 5) * 64;
        const int n = nh / Hh, h = nh - n * Hh;

        // ---- stage K, V (full head) and Q (64 rows, clamped) via cp.async --
        {
            const float* kp = Kh + (size_t)nh * LHD;
            const float* vp = Vh + (size_t)nh * LHD;
            for (int idx = t; idx < Lq * 16; idx += NTHR) {
                int r = idx >> 4, c4 = (idx & 15) * 4;
                cp_async16(&Ks[r * SKA + c4], kp + r * HD + c4);
                cp_async16(&Vs[r * SKA + c4], vp + r * HD + c4);
            }
            const float* qp = Qh + (size_t)nh * LHD;
#pragma unroll
            for (int i = 0; i < 4; i++) {
                int idx = t + i * NTHR;
                int r = idx >> 4, c4 = (idx & 15) * 4;
                int lg = lBase + r; if (lg >= Lq) lg = Lq - 1;
                cp_async16(&Qs[r * SKA + c4], qp + lg * HD + c4);
            }
            // zero V pad rows 257..263 (mma K-padding)
            if (t < 112) {
                int pr = 257 + t / 16, pc = (t % 16) * 4;
                *(float4*)(Vs + pr * SKA + pc) = make_float4(0.f, 0.f, 0.f, 0.f);
            }
        }
        cp_commit();
        cp_wait0();
        __syncthreads();

        // ---- round V in place to tf32 (mma input) --------------------------
        for (int idx = t; idx < Lq * 16; idx += NTHR) {
            int r = idx >> 4, c4 = (idx & 15) * 4;
            float4 v = *(const float4*)(Vs + r * SKA + c4);
            v.x = round_tf32(v.x); v.y = round_tf32(v.y);
            v.z = round_tf32(v.z); v.w = round_tf32(v.w);
            *(float4*)(Vs + r * SKA + c4) = v;
        }

        // ---- scores (fp32, per-row order identical to R16) -----------------
        int moff[9];
#pragma unroll
        for (int j = 0; j < 9; j++) {
            int m = j * 32 + lane;
            moff[j] = (m < Lq ? m : Lq - 1) * SKA;
        }

        float acc[8][9];
#pragma unroll
        for (int i = 0; i < 8; i++)
#pragma unroll
            for (int j = 0; j < 9; j++) acc[i][j] = 0.0f;

        const int wrow = wid * 8;
#pragma unroll 1
        for (int p = 0; p < 16; p++) {
            float4 q[8];
#pragma unroll
            for (int i = 0; i < 8; i++)
                q[i] = *(const float4*)(Qs + (wrow + i) * SKA + p * 4);
#pragma unroll
            for (int j = 0; j < 9; j++) {
                float4 k4 = *(const float4*)(Ks + moff[j] + p * 4);
#pragma unroll
                for (int i = 0; i < 8; i++) {
                    acc[i][j] = fmaf(q[i].x, k4.x, acc[i][j]);
                    acc[i][j] = fmaf(q[i].y, k4.y, acc[i][j]);
                    acc[i][j] = fmaf(q[i].z, k4.z, acc[i][j]);
                    acc[i][j] = fmaf(q[i].w, k4.w, acc[i][j]);
                }
            }
        }

        // ---- softmax (in regs) + gmem weights store ------------------------
#pragma unroll
        for (int i = 0; i < 8; i++) {
            int row = lBase + wrow + i;
            float mx = -INFINITY;
#pragma unroll
            for (int j = 0; j < 9; j++) {
                bool valid = (j * 32 + lane) < Lq;
                acc[i][j] = valid ? acc[i][j] * 0.125f : -INFINITY;
                mx = fmaxf(mx, acc[i][j]);
            }
#pragma unroll
            for (int off = 16; off > 0; off >>= 1)
                mx = fmaxf(mx, __shfl_xor_sync(0xffffffffu, mx, off));
            float s = 0.0f;
#pragma unroll
            for (int j = 0; j < 9; j++) {
                acc[i][j] = expf(acc[i][j] - mx);
                s += acc[i][j];
            }
#pragma unroll
            for (int off = 16; off > 0; off >>= 1)
                s += __shfl_xor_sync(0xffffffffu, s, off);
            float inv = 1.0f / s;
#pragma unroll
            for (int j = 0; j < 9; j++) acc[i][j] *= inv;   // final weights

            if (row < Lq) {
                float* wr = w + ((size_t)nh * Lq + row) * Lq;
#pragma unroll
                for (int j = 0; j < 9; j++) {
                    int m = j * 32 + lane;
                    if (m < Lq) wr[m] = acc[i][j];
                }
            }
        }
        __syncthreads();   // all warps done reading Ks before Ws overlays it

        // ---- write tf32 weights into Ws (overlaying Ks) --------------------
#pragma unroll
        for (int i = 0; i < 8; i++) {
            float* wsr = Ws + (wrow + i) * WSK;
#pragma unroll
            for (int j = 0; j < 9; j++) {
                int m = j * 32 + lane;
                if (m < WSK) wsr[m] = round_tf32(acc[i][j]);
            }
        }
        __syncthreads();   // Ws + rounded Vs ready

        // ---- attnV via tf32 MMA: attn[64 l][64 hd] = Ws @ Vs ---------------
        {
            const int m0 = (wid >> 1) * 16;   // 4 m-tiles over 8 warps
            const int ntb = (wid & 1) * 4;    // 4 n-tiles each
            float c[4][4];
#pragma unroll
            for (int nt = 0; nt < 4; nt++)
#pragma unroll
                for (int q = 0; q < 4; q++) c[nt][q] = 0.0f;

#pragma unroll 4
            for (int ks = 0; ks < 33; ks++) {
                int kk = ks * 8 + tq;
                uint32_t a[4];
                a[0] = __float_as_uint(Ws[(m0 + g)     * WSK + kk]);
                a[1] = __float_as_uint(Ws[(m0 + g + 8) * WSK + kk]);
                a[2] = __float_as_uint(Ws[(m0 + g)     * WSK + kk + 4]);
                a[3] = __float_as_uint(Ws[(m0 + g + 8) * WSK + kk + 4]);
#pragma unroll
                for (int nt = 0; nt < 4; nt++) {
                    int n0 = (ntb + nt) * 8;
                    uint32_t b[2];
                    b[0] = __float_as_uint(Vs[kk       * SKA + n0 + g]);
                    b[1] = __float_as_uint(Vs[(kk + 4) * SKA + n0 + g]);
                    mma_tf32(c[nt], a, b);
                }
            }
#pragma unroll
            for (int nt = 0; nt < 4; nt++) {
                int colBase = h * HD + (ntb + nt) * 8 + 2 * tq;
                int l0 = lBase + m0 + g;
                if (l0 < Lq) {
                    float* p = attnOut + ((size_t)l0 * Nb + n) * Dm + colBase;
                    p[0] = round_tf32(c[nt][0]); p[1] = round_tf32(c[nt][1]);
                }
                int l1 = l0 + 8;
                if (l1 < Lq) {
                    float* p = attnOut + ((size_t)l1 * Nb + n) * Dm + colBase;
                    p[0] = round_tf32(c[nt][2]); p[1] = round_tf32(c[nt][3]);
                }
            }
        }
        __syncthreads();   // before next unit overwrites smem
    }
}

// ---------------- the single fused kernel ------------------------------------
#define DSMEM_BYTES (ATTN_FLOATS * 4)   // 161,024 B

__global__ void __launch_bounds__(NTHR, 1)
fused_block(const float* __restrict__ x,
            const float* __restrict__ in_proj_w,
            const float* __restrict__ in_proj_b,
            const float* __restrict__ out_proj_w,
            const float* __restrict__ out_proj_b,
            const float* __restrict__ ln1_g, const float* __restrict__ ln1_b,
            const float* __restrict__ ln2_g, const float* __restrict__ ln2_b,
            const float* __restrict__ fc_w,  const float* __restrict__ fc_b,
            float* __restrict__ out_x, float* __restrict__ out_w) {
    extern __shared__ float dsm[];

    // 1) LN1 + round weights
    ln_phase(x, ln1_g, ln1_b, g_h);
    round_phase(in_proj_w,  g_win,  (D3 * Dm) / 4);
    round_phase(out_proj_w, g_wout, (Dm * Dm) / 4);
    round_phase(fc_w,       g_wfc,  (Dm * Dm) / 4);
    grid_bar(0);

    // 2) qkv = g_h @ win^T + b  -> head-major g_qkv
    gemm_phase(g_h, g_win, in_proj_b, nullptr, g_qkv,
               D3 / 256, (D3 / 256) * 129, 4, dsm);
    grid_bar(1);

    // 3) fused attention: scores + softmax -> out_w; attnV -> g_attn
    attn_phase(g_qkv, g_qkv + X_ELEMS, g_qkv + 2 * X_ELEMS,
               out_w, g_attn, dsm);
    grid_bar(2);

    // 4) x1 = x + attn @ wout^T + b
    gemm_phase(g_attn, g_wout, out_proj_b, x, g_x1,
               Dm / 256, (Dm / 256) * 129, 2, dsm);
    grid_bar(3);

    // 5) LN2: x1 -> g_h (rounded)
    ln_phase(g_x1, ln2_g, ln2_b, g_h);
    grid_bar(4);

    // 6) out_x = x1 + quickGELU(g_h @ wfc^T + fc_b)
    gemm_phase(g_h, g_wfc, fc_b, g_x1, out_x,
               Dm / 256, (Dm / 256) * 129, 3, dsm);
}

// ---------------------------------------------------------------------------
extern "C" void kernel_launch(void* const* d_in, const int* in_sizes, int n_in,
                              void* d_out, int out_size) {
    const float* x          = (const float*)d_in[0];
    const float* in_proj_w  = (const float*)d_in[1];
    const float* in_proj_b  = (const float*)d_in[2];
    const float* out_proj_w = (const float*)d_in[3];
    const float* out_proj_b = (const float*)d_in[4];
    const float* ln1_g      = (const float*)d_in[5];
    const float* ln1_b      = (const float*)d_in[6];
    const float* ln2_g      = (const float*)d_in[7];
    const float* ln2_b      = (const float*)d_in[8];
    const float* fc_w       = (const float*)d_in[9];
    const float* fc_b       = (const float*)d_in[10];

    float* out_x = (float*)d_out;
    float* out_w = (float*)d_out + X_ELEMS;

    static int configured = 0;
    if (!configured) {
        cudaFuncSetAttribute(fused_block,
                             cudaFuncAttributeMaxDynamicSharedMemorySize,
                             DSMEM_BYTES);
        configured = 1;
    }

    fused_block<<<NBLK, NTHR, DSMEM_BYTES>>>(
        x, in_proj_w, in_proj_b, out_proj_w, out_proj_b,
        ln1_g, ln1_b, ln2_g, ln2_b, fc_w, fc_b, out_x, out_w);
}